// round 10
// baseline (speedup 1.0000x reference)
#include <cuda_runtime.h>
#include <math.h>
#include <stdint.h>

// Problem constants
// B=4, N=4096, DIM=1024, HEADS=16, DIM_HEAD=64, M=128, DIM_INNER=1024
#define SCALE_A 0.125f   // 64^-0.5

// ---------------- scratch (device globals; no runtime allocation) ----------------
// RULE (learned R2, re-learned R8): device globals may ONLY be referenced from
// device code. Host-side symbol addresses are invalid (GB300 ATS makes it silent).
__device__ float g_qkv[50331648];    // [4,4096,3072]
__device__ float g_qa[33554432];     // qa_attn  [b,h,n,m]  (m fastest)
__device__ float g_qam[33554432];    // qa mixed [b,g,n,m]
__device__ float g_ak[33554432];     // ak raw sims [b,h,m,n] (n fastest)
__device__ float g_akm[33554432];    // ak mixed (softmaxed) [b,g,m,n]
__device__ float2 g_akpart[262144];  // partial stats [b,h,m][32 ntiles]
__device__ float2 g_akstat[8192];    // per (b,h,m): {rowmax, 1/sumexp}
__device__ float g_ao[524288];       // agent_out [b,g,m=128,d=64]
__device__ float g_aop[2097152];     // agent_out partials [4 splits][b,g,m,d]
__device__ float g_outpre[16777216]; // [b,n,1024] pre-projection, masked
__device__ unsigned char g_mask[16384]; // canonical uint8 mask [b,n]
__device__ float g_pA[16777216];     // packed A (16384x1024), reused by both GEMMs
__device__ float g_pBq[3145728];     // packed W_qkv (1024x3072)
__device__ float g_pBo[1048576];     // packed W_out (1024x1024)

// ---------------- helpers ----------------
__device__ __forceinline__ unsigned f2tf32(float x) {
    unsigned r;
    asm("cvt.rna.tf32.f32 %0, %1;" : "=r"(r) : "f"(x));
    return r;
}
__device__ __forceinline__ uint32_t smem_u32(const void* p) {
    uint32_t a;
    asm("{ .reg .u64 t; cvta.to.shared.u64 t, %1; cvt.u32.u64 %0, t; }" : "=r"(a) : "l"(p));
    return a;
}
__device__ __forceinline__ void cp16(uint32_t saddr, const void* g) {
    asm volatile("cp.async.cg.shared.global [%0], [%1], 16;" :: "r"(saddr), "l"(g));
}
__device__ __forceinline__ void mma_tf32(float* c, const unsigned* a,
                                         unsigned b0, unsigned b1) {
    asm volatile(
        "mma.sync.aligned.m16n8k8.row.col.f32.tf32.tf32.f32 "
        "{%0,%1,%2,%3}, {%4,%5,%6,%7}, {%8,%9}, {%0,%1,%2,%3};"
        : "+f"(c[0]), "+f"(c[1]), "+f"(c[2]), "+f"(c[3])
        : "r"(a[0]), "r"(a[1]), "r"(a[2]), "r"(a[3]), "r"(b0), "r"(b1));
}

// ---------------- mask canonicalization ----------------
__global__ void k_mask_canon(const void* __restrict__ mraw) {
    __shared__ int notI32, notF32;
    if (threadIdx.x == 0) { notI32 = 0; notF32 = 0; }
    __syncthreads();
    const unsigned int* w = (const unsigned int*)mraw;
    int a = 0, b = 0;
    for (int i = threadIdx.x; i < 4096; i += 256) {
        unsigned int v = w[i];
        if (v > 1u) a = 1;
        if (v != 0u && v != 0x3F800000u) b = 1;
    }
    if (a) atomicOr(&notI32, 1);
    if (b) atomicOr(&notF32, 1);
    __syncthreads();
    const int mode = notI32 ? (notF32 ? 2 : 1) : 0;
    for (int i = threadIdx.x; i < 16384; i += 256) {
        unsigned char mv;
        if (mode == 0)      mv = (((const int*)mraw)[i] != 0);
        else if (mode == 1) mv = (((const float*)mraw)[i] != 0.0f);
        else                mv = (((const unsigned char*)mraw)[i] != 0);
        g_mask[i] = mv;
    }
}

// ---------------- operand pack: A via smem transpose (coalesced stores) ----------------
// Packed A layout (verified R7/R9): element A[r][k] ->
//   rowtile=r>>8, blk=(r>>4)&15, gidE=r&7, hb=(r>>3)&1
//   c=k>>5, ks=(k>>3)&3, tig=k&3, hi=(k>>2)&1
//   lane=(gidE*4+tig)^ks, j=hi*2+hb
//   idx = (rowtile*(K/32)+c)*8192 + ((blk*4+ks)*32+lane)*4 + j
// Block = one (rowtile, c): load 256x32 tile coalesced, emit 8192 packed words
// as coalesced uint4 stores (decode word -> (r_local,k_local) -> smem read).
__device__ __forceinline__ void packA_body(const float* __restrict__ src,
                                           float* __restrict__ dst, int K) {
    __shared__ float tile[8192];   // [256 r][32 k]
    const int c = blockIdx.x;      // K chunk
    const int rowtile = blockIdx.y;
    const int t = threadIdx.x;
    const int nc = K >> 5;

    const float4* srow = (const float4*)(src + ((size_t)(rowtile * 256 + t)) * K + c * 32);
    float4* td = (float4*)(tile + t * 32);
#pragma unroll
    for (int i = 0; i < 8; i++) td[i] = srow[i];
    __syncthreads();

    float* dstb = dst + ((size_t)rowtile * nc + c) * 8192;
#pragma unroll
    for (int i = 0; i < 8; i++) {
        const int w4 = i * 256 + t;       // uint4 index; stores coalesced across t
        uint4 q;
        unsigned* qe = &q.x;
#pragma unroll
        for (int e = 0; e < 4; e++) {
            const int w = w4 * 4 + e;
            const int quad = w >> 2, j = w & 3;
            const int lane = quad & 31;
            const int ks = (quad >> 5) & 3;
            const int blk = quad >> 7;
            const int gidE = ((lane ^ ks) >> 2) & 7;
            const int tig = (lane ^ ks) & 3;
            const int hb = j & 1, hi = j >> 1;
            const int r_local = blk * 16 + hb * 8 + gidE;
            const int k_local = ks * 8 + hi * 4 + tig;
            qe[e] = f2tf32(tile[r_local * 32 + k_local]);
        }
        *(uint4*)(dstb + w4 * 4) = q;
    }
}

// B layout (verified R9): W[k][n] row-major (K x N):
//   coltile=n>>7, nblk=(n>>3)&15, gidE=n&7
//   c=k>>5, ks=(k>>3)&3, tig=k&3, v=(k>>2)&1
//   lane=(gidE*4+tig)^nblk
//   idx = (coltile*(K/32)+c)*4096 + ((nblk*4+ks)*32+lane)*2 + v
__device__ __forceinline__ void packB_body(const float* __restrict__ src,
                                           float* __restrict__ dst, int N, int K) {
    const size_t t = (size_t)blockIdx.x * 256 + threadIdx.x;
    const int nq = N >> 2;
    const int k = (int)(t / nq);
    const int n4 = (int)(t % nq) * 4;
    float4 v = *(const float4*)(src + (size_t)k * N + n4);
    const int nc = K >> 5;
    const int c = k >> 5, ks = (k >> 3) & 3, tig = k & 3, vb = (k >> 2) & 1;
    const float vv[4] = {v.x, v.y, v.z, v.w};
#pragma unroll
    for (int e = 0; e < 4; e++) {
        int n = n4 + e;
        int coltile = n >> 7, nblk = (n >> 3) & 15, gidE = n & 7;
        int lane = (gidE * 4 + tig) ^ nblk;
        dst[((size_t)coltile * nc + c) * 4096 + ((nblk * 4 + ks) * 32 + lane) * 2 + vb] =
            __uint_as_float(f2tf32(vv[e]));
    }
}

// Wrappers: device globals bound in DEVICE code.
__global__ __launch_bounds__(256) void k_packA_x(const float* __restrict__ x) {
    packA_body(x, g_pA, 1024);
}
__global__ __launch_bounds__(256) void k_packA_outpre() {
    packA_body(g_outpre, g_pA, 1024);
}
__global__ __launch_bounds__(256) void k_packB_qkv(const float* __restrict__ w) {
    packB_body(w, g_pBq, 3072, 1024);
}
__global__ __launch_bounds__(256) void k_packB_out(const float* __restrict__ w) {
    packB_body(w, g_pBo, 1024, 1024);
}

// ---------------- packed tf32 GEMM: C[M,N] = A @ B ----------------
// CTA 256m x 128n, 8 warps (4m x 2n), warp tile 64x64, BK=32,
// 3-stage cp.async pipeline, ONE __syncthreads per chunk.
#define G2_BUF_WORDS 12288            // A 8192 + B 4096
#define G2_SMEM_BYTES (3 * G2_BUF_WORDS * 4)   // 147456

__device__ __forceinline__ void gemm_packed_body(const float* __restrict__ gA,
                                                 const float* __restrict__ gB,
                                                 float* __restrict__ C,
                                                 int N, int K) {
    extern __shared__ unsigned dsm[];
    unsigned* bufs[3] = {dsm, dsm + G2_BUF_WORDS, dsm + 2 * G2_BUF_WORDS};
    const uint32_t sb0 = smem_u32(dsm);

    const int tid = threadIdx.x;
    const int warp = tid >> 5, lane = tid & 31;
    const int gid = lane >> 2, tig = lane & 3;
    const int wr = warp & 3, wq = warp >> 2;
    const int nc = K >> 5;

    const char* Asrc = (const char*)(gA + (size_t)blockIdx.y * nc * 8192);
    const char* Bsrc = (const char*)(gB + (size_t)blockIdx.x * nc * 4096);

    float acc[4][8][4];
#pragma unroll
    for (int i = 0; i < 4; i++)
#pragma unroll
        for (int j = 0; j < 8; j++)
#pragma unroll
            for (int l = 0; l < 4; l++) acc[i][j][l] = 0.f;

    auto issue = [&](int s, int c) {
        const uint32_t sbuf = sb0 + s * (G2_BUF_WORDS * 4);
        const char* a = Asrc + (size_t)c * 32768;
        const char* b = Bsrc + (size_t)c * 16384;
#pragma unroll
        for (int i = 0; i < 8; i++) {
            int off = (tid + i * 256) * 16;
            cp16(sbuf + off, a + off);
        }
#pragma unroll
        for (int i = 0; i < 4; i++) {
            int off = (tid + i * 256) * 16;
            cp16(sbuf + 32768 + off, b + off);
        }
        asm volatile("cp.async.commit_group;" ::: "memory");
    };

    issue(0, 0);
    if (nc > 1) issue(1, 1);

    int cur = 0;           // c % 3
    for (int c = 0; c < nc; c++) {
        if (c + 1 < nc) {
            asm volatile("cp.async.wait_group 1;" ::: "memory");
        } else {
            asm volatile("cp.async.wait_group 0;" ::: "memory");
        }
        __syncthreads();   // all warps done computing buffer (c+2)%3 (= c-1's buffer)
        if (c + 2 < nc) {
            int nxt = cur + 2; if (nxt >= 3) nxt -= 3;
            issue(nxt, c + 2);
        }
        const unsigned* Ap = bufs[cur];
        const unsigned* Bp = Ap + 8192;
#pragma unroll
        for (int ks = 0; ks < 4; ks++) {
            uint4 a[4];
#pragma unroll
            for (int mt = 0; mt < 4; mt++)
                a[mt] = *(const uint4*)&Ap[(((wr * 4 + mt) * 4 + ks) * 32 + (lane ^ ks)) * 4];
#pragma unroll
            for (int nt = 0; nt < 8; nt++) {
                int nblk = wq * 8 + nt;
                uint2 bb = *(const uint2*)&Bp[((nblk * 4 + ks) * 32 + (lane ^ nblk)) * 2];
#pragma unroll
                for (int mt = 0; mt < 4; mt++)
                    mma_tf32(acc[mt][nt], (const unsigned*)&a[mt], bb.x, bb.y);
            }
        }
        cur++; if (cur >= 3) cur -= 3;
    }

    float* Cb = C + (size_t)(blockIdx.y * 256) * N + blockIdx.x * 128;
#pragma unroll
    for (int mt = 0; mt < 4; mt++) {
#pragma unroll
        for (int nt = 0; nt < 8; nt++) {
            int r = wr * 64 + mt * 16 + gid;
            int cc = wq * 64 + nt * 8 + tig * 2;
            *(float2*)(Cb + (size_t)r * N + cc) =
                make_float2(acc[mt][nt][0], acc[mt][nt][1]);
            *(float2*)(Cb + (size_t)(r + 8) * N + cc) =
                make_float2(acc[mt][nt][2], acc[mt][nt][3]);
        }
    }
}

__global__ __launch_bounds__(256, 1) void k_gemm_qkv() {
    gemm_packed_body(g_pA, g_pBq, g_qkv, 3072, 1024);
}
__global__ __launch_bounds__(256, 1) void k_gemm_out(float* __restrict__ out) {
    gemm_packed_body(g_pA, g_pBo, out, 1024, 1024);
}

// ---------------- qa: register-tiled sim GEMM + fused softmax over m ----------------
__global__ __launch_bounds__(256) void k_qa(const float* __restrict__ agent) {
    extern __shared__ float fsm[];
    float* Qs = fsm;          // [64k][128n]
    float* Ams = fsm + 8192;  // [64k][128m]
    const int b = blockIdx.z, h = blockIdx.y, n0 = blockIdx.x * 128;
    const int t = threadIdx.x;

    {
        int m = t >> 1, kb = (t & 1) * 32;
        const float4* src = (const float4*)(agent + h * 8192 + m * 64 + kb);
#pragma unroll
        for (int i = 0; i < 8; i++) {
            float4 v = src[i];
            int k = kb + i * 4;
            Ams[(k + 0) * 128 + m] = v.x * SCALE_A;
            Ams[(k + 1) * 128 + m] = v.y * SCALE_A;
            Ams[(k + 2) * 128 + m] = v.z * SCALE_A;
            Ams[(k + 3) * 128 + m] = v.w * SCALE_A;
        }
    }
    {
        int n = t >> 1, kb = (t & 1) * 32;
        const float4* src = (const float4*)(g_qkv + ((size_t)(b * 4096 + n0 + n)) * 3072 + h * 64 + kb);
#pragma unroll
        for (int i = 0; i < 8; i++) {
            float4 v = src[i];
            int k = kb + i * 4;
            Qs[(k + 0) * 128 + n] = v.x;
            Qs[(k + 1) * 128 + n] = v.y;
            Qs[(k + 2) * 128 + n] = v.z;
            Qs[(k + 3) * 128 + n] = v.w;
        }
    }
    __syncthreads();

    const int tx = t & 15, ty = t >> 4;
    float acc[8][8];
#pragma unroll
    for (int i = 0; i < 8; i++)
#pragma unroll
        for (int j = 0; j < 8; j++) acc[i][j] = 0.f;

#pragma unroll 4
    for (int kk = 0; kk < 64; kk++) {
        float4 q0 = *(const float4*)&Qs[kk * 128 + ty * 4];
        float4 q1 = *(const float4*)&Qs[kk * 128 + 64 + ty * 4];
        float4 a0 = *(const float4*)&Ams[kk * 128 + tx * 4];
        float4 a1 = *(const float4*)&Ams[kk * 128 + 64 + tx * 4];
        const float qn[8] = {q0.x, q0.y, q0.z, q0.w, q1.x, q1.y, q1.z, q1.w};
        const float am[8] = {a0.x, a0.y, a0.z, a0.w, a1.x, a1.y, a1.z, a1.w};
#pragma unroll
        for (int i = 0; i < 8; i++)
#pragma unroll
            for (int j = 0; j < 8; j++) acc[i][j] += qn[i] * am[j];
    }

    const size_t base = ((size_t)(b * 16 + h)) * 524288;
#pragma unroll
    for (int i = 0; i < 8; i++) {
        float mx = acc[i][0];
#pragma unroll
        for (int j = 1; j < 8; j++) mx = fmaxf(mx, acc[i][j]);
#pragma unroll
        for (int off = 8; off > 0; off >>= 1)
            mx = fmaxf(mx, __shfl_xor_sync(0xffffffffu, mx, off));
        float e[8], sum = 0.f;
#pragma unroll
        for (int j = 0; j < 8; j++) { e[j] = __expf(acc[i][j] - mx); sum += e[j]; }
#pragma unroll
        for (int off = 8; off > 0; off >>= 1)
            sum += __shfl_xor_sync(0xffffffffu, sum, off);
        const float inv = 1.f / sum;
        const int n_i = n0 + ((i < 4) ? (ty * 4 + i) : (64 + ty * 4 + i - 4));
        float* row = g_qa + base + (size_t)n_i * 128;
        *(float4*)(row + tx * 4) = make_float4(e[0] * inv, e[1] * inv, e[2] * inv, e[3] * inv);
        *(float4*)(row + 64 + tx * 4) = make_float4(e[4] * inv, e[5] * inv, e[6] * inv, e[7] * inv);
    }
}

// ---------------- ak: sim GEMM + fused PARTIAL softmax stats ----------------
__global__ __launch_bounds__(256) void k_ak_sim(const float* __restrict__ agent) {
    extern __shared__ float fsm[];
    float* Ks = fsm;          // [64k][128n]
    float* Ams = fsm + 8192;  // [64k][128m]
    const int b = blockIdx.z, h = blockIdx.y, n0 = blockIdx.x * 128;
    const int t = threadIdx.x;

    {
        int m = t >> 1, kb = (t & 1) * 32;
        const float4* src = (const float4*)(agent + h * 8192 + m * 64 + kb);
#pragma unroll
        for (int i = 0; i < 8; i++) {
            float4 v = src[i];
            int k = kb + i * 4;
            Ams[(k + 0) * 128 + m] = v.x * SCALE_A;
            Ams[(k + 1) * 128 + m] = v.y * SCALE_A;
            Ams[(k + 2) * 128 + m] = v.z * SCALE_A;
            Ams[(k + 3) * 128 + m] = v.w * SCALE_A;
        }
    }
    {
        int n = t >> 1, kb = (t & 1) * 32;
        const float4* src = (const float4*)(g_qkv + ((size_t)(b * 4096 + n0 + n)) * 3072 + 1024 + h * 64 + kb);
#pragma unroll
        for (int i = 0; i < 8; i++) {
            float4 v = src[i];
            int k = kb + i * 4;
            Ks[(k + 0) * 128 + n] = v.x;
            Ks[(k + 1) * 128 + n] = v.y;
            Ks[(k + 2) * 128 + n] = v.z;
            Ks[(k + 3) * 128 + n] = v.w;
        }
    }
    __syncthreads();

    const int tx = t & 15, ty = t >> 4;
    float acc[8][8];
#pragma unroll
    for (int i = 0; i < 8; i++)
#pragma unroll
        for (int j = 0; j < 8; j++) acc[i][j] = 0.f;

#pragma unroll 4
    for (int kk = 0; kk < 64; kk++) {
        float4 a0 = *(const float4*)&Ams[kk * 128 + ty * 4];
        float4 a1 = *(const float4*)&Ams[kk * 128 + 64 + ty * 4];
        float4 k0 = *(const float4*)&Ks[kk * 128 + tx * 4];
        float4 k1 = *(const float4*)&Ks[kk * 128 + 64 + tx * 4];
        const float am[8] = {a0.x, a0.y, a0.z, a0.w, a1.x, a1.y, a1.z, a1.w};
        const float kn[8] = {k0.x, k0.y, k0.z, k0.w, k1.x, k1.y, k1.z, k1.w};
#pragma unroll
        for (int i = 0; i < 8; i++)
#pragma unroll
            for (int j = 0; j < 8; j++) acc[i][j] += am[i] * kn[j];
    }

    // thread's n columns + mask
    const unsigned char* mrow = g_mask + b * 4096 + n0;
    bool mk[8];
#pragma unroll
    for (int j = 0; j < 4; j++) {
        mk[j] = mrow[tx * 4 + j] != 0;
        mk[4 + j] = mrow[64 + tx * 4 + j] != 0;
    }

    const size_t base = ((size_t)(b * 16 + h)) * 524288;
#pragma unroll
    for (int i = 0; i < 8; i++) {
        const int m_i = (i < 4) ? (ty * 4 + i) : (64 + ty * 4 + i - 4);
        float* row = g_ak + base + (size_t)m_i * 4096 + n0;
        *(float4*)(row + tx * 4) = make_float4(acc[i][0], acc[i][1], acc[i][2], acc[i][3]);
        *(float4*)(row + 64 + tx * 4) = make_float4(acc[i][4], acc[i][5], acc[i][6], acc[i][7]);

        // partial (max, sumexp) over this block's 128 n
        float mx = -3.402823e38f;
#pragma unroll
        for (int j = 0; j < 8; j++) mx = fmaxf(mx, mk[j] ? acc[i][j] : -3.402823e38f);
#pragma unroll
        for (int off = 8; off > 0; off >>= 1)
            mx = fmaxf(mx, __shfl_xor_sync(0xffffffffu, mx, off));
        float sm = 0.f;
#pragma unroll
        for (int j = 0; j < 8; j++) sm += mk[j] ? __expf(acc[i][j] - mx) : 0.f;
#pragma unroll
        for (int off = 8; off > 0; off >>= 1)
            sm += __shfl_xor_sync(0xffffffffu, sm, off);
        if (tx == 0)
            g_akpart[((size_t)((b * 16 + h) * 128 + m_i)) * 32 + blockIdx.x] =
                make_float2(mx, sm);
    }
}

// ---------------- combine partial stats -> g_akstat ----------------
__global__ __launch_bounds__(256) void k_ak_comb() {
    const int row = blockIdx.x * 256 + threadIdx.x;   // 8192 rows
    const float2* p = g_akpart + (size_t)row * 32;
    float mx = -3.402823e38f, sum = 0.f;
#pragma unroll 8
    for (int i = 0; i < 32; i++) {
        float2 q = p[i];
        float nm = fmaxf(mx, q.x);
        sum = sum * __expf(mx - nm) + q.y * __expf(q.x - nm);
        mx = nm;
    }
    g_akstat[row] = make_float2(mx, 1.f / sum);
}

// ---------------- talking-heads mixes (float4 vectorized) ----------------
__global__ __launch_bounds__(256) void k_mix_qa(const float* __restrict__ W) {
    __shared__ float Ws[256];
    Ws[threadIdx.x] = W[threadIdx.x];
    __syncthreads();
    const size_t S = 524288;
    const int b = blockIdx.y;
    const size_t s = ((size_t)blockIdx.x * 256 + threadIdx.x) * 4;
    float4 v[16];
#pragma unroll
    for (int h = 0; h < 16; h++)
        v[h] = *(const float4*)(g_qa + (size_t)(b * 16 + h) * S + s);
#pragma unroll
    for (int g = 0; g < 16; g++) {
        float4 o = make_float4(0.f, 0.f, 0.f, 0.f);
#pragma unroll
        for (int h = 0; h < 16; h++) {
            float w = Ws[g * 16 + h];
            o.x += w * v[h].x; o.y += w * v[h].y;
            o.z += w * v[h].z; o.w += w * v[h].w;
        }
        *(float4*)(g_qam + (size_t)(b * 16 + g) * S + s) = o;
    }
}

__global__ __launch_bounds__(256) void k_mix_ak(const float* __restrict__ W) {
    __shared__ float Ws[256];
    Ws[threadIdx.x] = W[threadIdx.x];
    __syncthreads();
    const size_t S = 524288;
    const int b = blockIdx.y;
    const size_t s = ((size_t)blockIdx.x * 256 + threadIdx.x) * 4;
    const int m = (int)(s >> 12);
    const int n = (int)(s & 4095);
    const uchar4 mk = *(const uchar4*)(g_mask + b * 4096 + n);
    float4 v[16];
#pragma unroll
    for (int h = 0; h < 16; h++) {
        float4 raw = *(const float4*)(g_ak + (size_t)(b * 16 + h) * S + s);
        float2 st = g_akstat[(b * 16 + h) * 128 + m];
        v[h].x = mk.x ? __expf(raw.x - st.x) * st.y : 0.f;
        v[h].y = mk.y ? __expf(raw.y - st.x) * st.y : 0.f;
        v[h].z = mk.z ? __expf(raw.z - st.x) * st.y : 0.f;
        v[h].w = mk.w ? __expf(raw.w - st.x) * st.y : 0.f;
    }
#pragma unroll
    for (int g = 0; g < 16; g++) {
        float4 o = make_float4(0.f, 0.f, 0.f, 0.f);
#pragma unroll
        for (int h = 0; h < 16; h++) {
            float w = Ws[g * 16 + h];
            o.x += w * v[h].x; o.y += w * v[h].y;
            o.z += w * v[h].z; o.w += w * v[h].w;
        }
        *(float4*)(g_akm + (size_t)(b * 16 + g) * S + s) = o;
    }
}

// ---------------- agent_out partials: split n into 4 ranges ----------------
__global__ __launch_bounds__(512) void k_agent_out() {
    __shared__ float akm_s[128 * 64];
    __shared__ float v_s[64 * 64];
    const int g = blockIdx.x, b = blockIdx.y, sp = blockIdx.z;
    const int t = threadIdx.x;
    const int d = t & 63, mg = t >> 6;
    const float* akm_b = g_akm + (size_t)(b * 16 + g) * 128 * 4096;
    const float* v_b = g_qkv + (size_t)b * 4096 * 3072 + 2048 + g * 64;

    float acc[16];
#pragma unroll
    for (int j = 0; j < 16; j++) acc[j] = 0.f;

    const int nlo = sp * 1024, nhi = nlo + 1024;
    for (int n0 = nlo; n0 < nhi; n0 += 64) {
#pragma unroll
        for (int i = 0; i < 16; i++) {
            int idx = t + i * 512;
            int r = idx >> 6, c = idx & 63;
            akm_s[idx] = akm_b[(size_t)r * 4096 + n0 + c];
        }
#pragma unroll
        for (int i = 0; i < 8; i++) {
            int idx = t + i * 512;
            int r = idx >> 6, c = idx & 63;
            v_s[idx] = v_b[(size_t)(n0 + r) * 3072 + c];
        }
        __syncthreads();
#pragma unroll 4
        for (int nn = 0; nn < 64; nn++) {
            float vv = v_s[nn * 64 + d];
#pragma unroll
            for (int j = 0; j < 16; j++)
                acc[j] += akm_s[(mg * 16 + j) * 64 + nn] * vv;
        }
        __syncthreads();
    }
    float* out = g_aop + (size_t)sp * 524288 + (size_t)(b * 16 + g) * 8192;
#pragma unroll
    for (int j = 0; j < 16; j++) out[(mg * 16 + j) * 64 + d] = acc[j];
}

__global__ __launch_bounds__(256) void k_ao_reduce() {
    const int i = blockIdx.x * 256 + threadIdx.x;     // float4 index, 131072 total
    const float4* p = (const float4*)g_aop;
    float4 a = p[i], bq = p[131072 + i], c = p[262144 + i], d = p[393216 + i];
    ((float4*)g_ao)[i] = make_float4(a.x + bq.x + c.x + d.x, a.y + bq.y + c.y + d.y,
                                     a.z + bq.z + c.z + d.z, a.w + bq.w + c.w + d.w);
}

// ---------------- out_pre: [b,n,g*64+d] = sum_m qam[b,g,n,m]*ao[b,g,m,d], masked ----
__global__ __launch_bounds__(256) void k_out_pre() {
    extern __shared__ float fsm[];
    float* qs = fsm;          // [64m][128n]
    float* aos = fsm + 8192;  // [128m][64d]
    const int n0 = blockIdx.x * 128, g = blockIdx.y, b = blockIdx.z;
    const int t = threadIdx.x;
    const int tx = t & 15, ty = t >> 4;
    const float* qam_b = g_qam + (size_t)(b * 16 + g) * 524288;
    const float* ao_b = g_ao + (size_t)(b * 16 + g) * 8192;

#pragma unroll
    for (int i = 0; i < 8; i++) {
        int f = t + i * 256;
        int m = f >> 4, df = (f & 15) * 4;
        *(float4*)&aos[m * 64 + df] = *(const float4*)(ao_b + m * 64 + df);
    }

    float acc[8][4];
#pragma unroll
    for (int i = 0; i < 8; i++)
#pragma unroll
        for (int w = 0; w < 4; w++) acc[i][w] = 0.f;

    for (int mc = 0; mc < 128; mc += 64) {
        __syncthreads();
#pragma unroll
        for (int i = 0; i < 8; i++) {
            int f = t + i * 256;
            int n = f >> 4, mf = (f & 15) * 4;
            float4 v = *(const float4*)(qam_b + (size_t)(n0 + n) * 128 + mc + mf);
            qs[(mf + 0) * 128 + n] = v.x;
            qs[(mf + 1) * 128 + n] = v.y;
            qs[(mf + 2) * 128 + n] = v.z;
            qs[(mf + 3) * 128 + n] = v.w;
        }
        __syncthreads();
#pragma unroll 4
        for (int mm = 0; mm < 64; mm++) {
            float4 r0 = *(const float4*)&qs[mm * 128 + ty * 4];
            float4 r1 = *(const float4*)&qs[mm * 128 + 64 + ty * 4];
            float4 rb = *(const float4*)&aos[(mc + mm) * 64 + tx * 4];
            const float rn[8] = {r0.x, r0.y, r0.z, r0.w, r1.x, r1.y, r1.z, r1.w};
            const float* bw = &rb.x;
#pragma unroll
            for (int i = 0; i < 8; i++)
#pragma unroll
                for (int w = 0; w < 4; w++) acc[i][w] += rn[i] * bw[w];
        }
    }

#pragma unroll
    for (int i = 0; i < 8; i++) {
        const int n_i = n0 + ((i < 4) ? (ty * 4 + i) : (64 + ty * 4 + i - 4));
        const float msk = g_mask[b * 4096 + n_i] ? 1.f : 0.f;
        *(float4*)(g_outpre + ((size_t)(b * 4096 + n_i)) * 1024 + g * 64 + tx * 4) =
            make_float4(acc[i][0] * msk, acc[i][1] * msk, acc[i][2] * msk, acc[i][3] * msk);
    }
}

// ---------------- launch ----------------
extern "C" void kernel_launch(void* const* d_in, const int* in_sizes, int n_in,
                              void* d_out, int out_size) {
    const float* x = (const float*)d_in[0];
    const void* mask_raw = d_in[1];
    const float* W_qkv = (const float*)d_in[2];
    const float* agent = (const float*)d_in[3];
    const float* W_qa = (const float*)d_in[4];
    const float* W_ak = (const float*)d_in[5];
    const float* W_out = (const float*)d_in[6];
    float* out = (float*)d_out;

    cudaFuncSetAttribute(k_gemm_qkv, cudaFuncAttributeMaxDynamicSharedMemorySize, G2_SMEM_BYTES);
    cudaFuncSetAttribute(k_gemm_out, cudaFuncAttributeMaxDynamicSharedMemorySize, G2_SMEM_BYTES);
    cudaFuncSetAttribute(k_qa, cudaFuncAttributeMaxDynamicSharedMemorySize, 65536);
    cudaFuncSetAttribute(k_ak_sim, cudaFuncAttributeMaxDynamicSharedMemorySize, 65536);
    cudaFuncSetAttribute(k_out_pre, cudaFuncAttributeMaxDynamicSharedMemorySize, 65536);

    // 0. mask canonicalization + operand packing
    k_mask_canon<<<1, 256>>>(mask_raw);
    k_packB_qkv<<<3072, 256>>>(W_qkv);
    k_packB_out<<<1024, 256>>>(W_out);
    k_packA_x<<<dim3(32, 64), 256>>>(x);
    // 1. qkv projection (3-stage cp.async pipeline)
    k_gemm_qkv<<<dim3(3072 / 128, 16384 / 256), 256, G2_SMEM_BYTES>>>();
    // 2. qa similarities + fused softmax (over m) -> [b,h,n,m]
    k_qa<<<dim3(32, 16, 4), 256, 65536>>>(agent);
    // 3. ak similarities + fused partial softmax stats
    k_ak_sim<<<dim3(32, 16, 4), 256, 65536>>>(agent);
    // 4. combine partial stats (2MB read)
    k_ak_comb<<<32, 256>>>();
    // 5. talking heads (float4; ak mix applies softmax on the fly)
    k_mix_qa<<<dim3(512, 4), 256>>>(W_qa);
    k_mix_ak<<<dim3(512, 4), 256>>>(W_ak);
    // 6. agent_out = ak_mixed @ v (4-way n-split + reduce)
    k_agent_out<<<dim3(16, 4, 4), 512>>>();
    k_ao_reduce<<<512, 256>>>();
    // 7. out_pre = qam @ agent_out (+ output mask)
    k_out_pre<<<dim3(32, 16, 4), 256, 65536>>>();
    // 8. final projection (pack outpre, then packed GEMM)
    k_packA_outpre<<<dim3(32, 64), 256>>>();
    k_gemm_out<<<dim3(1024 / 128, 16384 / 256), 256, G2_SMEM_BYTES>>>(out);
}

// round 11
// speedup vs baseline: 1.0928x; 1.0928x over previous
#include <cuda_runtime.h>
#include <math.h>
#include <stdint.h>

// Problem constants
// B=4, N=4096, DIM=1024, HEADS=16, DIM_HEAD=64, M=128, DIM_INNER=1024
#define SCALE_A 0.125f   // 64^-0.5

// ---------------- scratch (device globals; no runtime allocation) ----------------
// RULE (learned R2, re-learned R8): device globals may ONLY be referenced from
// device code. Host-side symbol addresses are invalid (GB300 ATS makes it silent).
__device__ float g_qkv[50331648];    // [4,4096,3072]
__device__ float g_qa[33554432];     // qa_attn  [b,h,n,m]  (m fastest)
__device__ float g_qam[33554432];    // qa mixed [b,g,n,m]
__device__ float g_ak[33554432];     // ak raw sims [b,h,m,n] (n fastest)
__device__ float g_akm[33554432];    // ak mixed (softmaxed) [b,g,m,n]
__device__ float2 g_akpart[262144];  // partial stats [b,h,m][32 ntiles]
__device__ float2 g_akstat[8192];    // per (b,h,m): {rowmax, 1/sumexp}
__device__ float g_ao[524288];       // agent_out [b,g,m=128,d=64]
__device__ float g_aop[2097152];     // agent_out partials [4 splits][b,g,m,d]
__device__ float g_outpre[16777216]; // [b,n,1024] pre-projection, masked
__device__ unsigned char g_mask[16384]; // canonical uint8 mask [b,n]
__device__ float g_pA[16777216];     // packed A (16384x1024), reused by both GEMMs
__device__ float g_pBq[3145728];     // packed W_qkv (1024x3072)
__device__ float g_pBo[1048576];     // packed W_out (1024x1024)

// ---------------- helpers ----------------
__device__ __forceinline__ unsigned f2tf32(float x) {
    unsigned r;
    asm("cvt.rna.tf32.f32 %0, %1;" : "=r"(r) : "f"(x));
    return r;
}
__device__ __forceinline__ uint32_t smem_u32(const void* p) {
    uint32_t a;
    asm("{ .reg .u64 t; cvta.to.shared.u64 t, %1; cvt.u32.u64 %0, t; }" : "=r"(a) : "l"(p));
    return a;
}
__device__ __forceinline__ void cp16(uint32_t saddr, const void* g) {
    asm volatile("cp.async.cg.shared.global [%0], [%1], 16;" :: "r"(saddr), "l"(g));
}
__device__ __forceinline__ void mma_tf32(float* c, const unsigned* a,
                                         unsigned b0, unsigned b1) {
    asm volatile(
        "mma.sync.aligned.m16n8k8.row.col.f32.tf32.tf32.f32 "
        "{%0,%1,%2,%3}, {%4,%5,%6,%7}, {%8,%9}, {%0,%1,%2,%3};"
        : "+f"(c[0]), "+f"(c[1]), "+f"(c[2]), "+f"(c[3])
        : "r"(a[0]), "r"(a[1]), "r"(a[2]), "r"(a[3]), "r"(b0), "r"(b1));
}

// ---------------- mask canonicalization ----------------
__global__ void k_mask_canon(const void* __restrict__ mraw) {
    __shared__ int notI32, notF32;
    if (threadIdx.x == 0) { notI32 = 0; notF32 = 0; }
    __syncthreads();
    const unsigned int* w = (const unsigned int*)mraw;
    int a = 0, b = 0;
    for (int i = threadIdx.x; i < 4096; i += 256) {
        unsigned int v = w[i];
        if (v > 1u) a = 1;
        if (v != 0u && v != 0x3F800000u) b = 1;
    }
    if (a) atomicOr(&notI32, 1);
    if (b) atomicOr(&notF32, 1);
    __syncthreads();
    const int mode = notI32 ? (notF32 ? 2 : 1) : 0;
    for (int i = threadIdx.x; i < 16384; i += 256) {
        unsigned char mv;
        if (mode == 0)      mv = (((const int*)mraw)[i] != 0);
        else if (mode == 1) mv = (((const float*)mraw)[i] != 0.0f);
        else                mv = (((const unsigned char*)mraw)[i] != 0);
        g_mask[i] = mv;
    }
}

// ---------------- operand pack bodies (R9 versions — known good) ----------------
// A layout: for row r, col k (K cols):
//   rowtile=r>>8, blk=(r>>4)&15, gidE=r&7, hb=(r>>3)&1
//   c=k>>5, ks=(k>>3)&3, tig=k&3, hi=(k>>2)&1
//   lane=(gidE*4+tig)^ks, j=hi*2+hb
//   idx = (rowtile*(K/32)+c)*8192 + ((blk*4+ks)*32+lane)*4 + j
__device__ __forceinline__ void packA_body(const float* __restrict__ src,
                                           float* __restrict__ dst, int K) {
    const size_t t = (size_t)blockIdx.x * 256 + threadIdx.x;
    const int kq = K >> 2;
    const int r = (int)(t / kq);
    const int k4 = (int)(t % kq) * 4;
    float4 v = *(const float4*)(src + (size_t)r * K + k4);
    const int nc = K >> 5;
    const int rowtile = r >> 8, blk = (r >> 4) & 15, gidE = r & 7, hb = (r >> 3) & 1;
    float* base = dst + (size_t)rowtile * nc * 8192;
    const float vv[4] = {v.x, v.y, v.z, v.w};
#pragma unroll
    for (int e = 0; e < 4; e++) {
        int k = k4 + e;
        int c = k >> 5, ks = (k >> 3) & 3, tig = k & 3, hi = (k >> 2) & 1;
        int lane = (gidE * 4 + tig) ^ ks;
        int j = hi * 2 + hb;
        base[(size_t)c * 8192 + ((blk * 4 + ks) * 32 + lane) * 4 + j] =
            __uint_as_float(f2tf32(vv[e]));
    }
}

// B layout: W[k][n] row-major (K x N):
//   coltile=n>>7, nblk=(n>>3)&15, gidE=n&7
//   c=k>>5, ks=(k>>3)&3, tig=k&3, v=(k>>2)&1
//   lane=(gidE*4+tig)^nblk
//   idx = (coltile*(K/32)+c)*4096 + ((nblk*4+ks)*32+lane)*2 + v
__device__ __forceinline__ void packB_body(const float* __restrict__ src,
                                           float* __restrict__ dst, int N, int K) {
    const size_t t = (size_t)blockIdx.x * 256 + threadIdx.x;
    const int nq = N >> 2;
    const int k = (int)(t / nq);
    const int n4 = (int)(t % nq) * 4;
    float4 v = *(const float4*)(src + (size_t)k * N + n4);
    const int nc = K >> 5;
    const int c = k >> 5, ks = (k >> 3) & 3, tig = k & 3, vb = (k >> 2) & 1;
    const float vv[4] = {v.x, v.y, v.z, v.w};
#pragma unroll
    for (int e = 0; e < 4; e++) {
        int n = n4 + e;
        int coltile = n >> 7, nblk = (n >> 3) & 15, gidE = n & 7;
        int lane = (gidE * 4 + tig) ^ nblk;
        dst[((size_t)coltile * nc + c) * 4096 + ((nblk * 4 + ks) * 32 + lane) * 2 + vb] =
            __uint_as_float(f2tf32(vv[e]));
    }
}

// Wrappers: device globals bound in DEVICE code.
__global__ __launch_bounds__(256) void k_packA_x(const float* __restrict__ x) {
    packA_body(x, g_pA, 1024);
}
__global__ __launch_bounds__(256) void k_packA_outpre() {
    packA_body(g_outpre, g_pA, 1024);
}
__global__ __launch_bounds__(256) void k_packB_qkv(const float* __restrict__ w) {
    packB_body(w, g_pBq, 3072, 1024);
}
__global__ __launch_bounds__(256) void k_packB_out(const float* __restrict__ w) {
    packB_body(w, g_pBo, 1024, 1024);
}

// ---------------- packed tf32 GEMM (R9 2-stage version — known good) ----------------
// CTA 256m x 128n, 8 warps (4m x 2n), warp tile 64x64, BK=32, cp.async double-buffer.
#define G2_STAGE_WORDS 12288          // A 8192 + B 4096
#define G2_SMEM_BYTES (2 * G2_STAGE_WORDS * 4)   // 98304

__device__ __forceinline__ void gemm_packed_body(const float* __restrict__ gA,
                                                 const float* __restrict__ gB,
                                                 float* __restrict__ C,
                                                 int N, int K) {
    extern __shared__ unsigned dsm[];
    unsigned* buf0 = dsm;
    unsigned* buf1 = dsm + G2_STAGE_WORDS;

    const int tid = threadIdx.x;
    const int warp = tid >> 5, lane = tid & 31;
    const int gid = lane >> 2, tig = lane & 3;
    const int wr = warp & 3, wq = warp >> 2;
    const int nc = K >> 5;

    const char* Asrc = (const char*)(gA + (size_t)blockIdx.y * nc * 8192);
    const char* Bsrc = (const char*)(gB + (size_t)blockIdx.x * nc * 4096);
    const uint32_t sA0 = smem_u32(buf0);
    const uint32_t sA1 = smem_u32(buf1);

    float acc[4][8][4];
#pragma unroll
    for (int i = 0; i < 4; i++)
#pragma unroll
        for (int j = 0; j < 8; j++)
#pragma unroll
            for (int l = 0; l < 4; l++) acc[i][j][l] = 0.f;

    auto issue = [&](uint32_t sbuf, int c) {
        const char* a = Asrc + (size_t)c * 32768;
        const char* b = Bsrc + (size_t)c * 16384;
#pragma unroll
        for (int i = 0; i < 8; i++) {
            int off = (tid + i * 256) * 16;
            cp16(sbuf + off, a + off);
        }
#pragma unroll
        for (int i = 0; i < 4; i++) {
            int off = (tid + i * 256) * 16;
            cp16(sbuf + 32768 + off, b + off);
        }
    };

    issue(sA0, 0);
    asm volatile("cp.async.commit_group;" ::: "memory");

    for (int c = 0; c < nc; c++) {
        const int cur = c & 1;
        if (c + 1 < nc) {
            issue(cur ? sA0 : sA1, c + 1);
            asm volatile("cp.async.commit_group;" ::: "memory");
            asm volatile("cp.async.wait_group 1;" ::: "memory");
        } else {
            asm volatile("cp.async.wait_group 0;" ::: "memory");
        }
        __syncthreads();
        const unsigned* Ap = cur ? buf1 : buf0;
        const unsigned* Bp = Ap + 8192;
#pragma unroll
        for (int ks = 0; ks < 4; ks++) {
            uint4 a[4];
#pragma unroll
            for (int mt = 0; mt < 4; mt++)
                a[mt] = *(const uint4*)&Ap[(((wr * 4 + mt) * 4 + ks) * 32 + (lane ^ ks)) * 4];
#pragma unroll
            for (int nt = 0; nt < 8; nt++) {
                int nblk = wq * 8 + nt;
                uint2 bb = *(const uint2*)&Bp[((nblk * 4 + ks) * 32 + (lane ^ nblk)) * 2];
#pragma unroll
                for (int mt = 0; mt < 4; mt++)
                    mma_tf32(acc[mt][nt], (const unsigned*)&a[mt], bb.x, bb.y);
            }
        }
        __syncthreads();
    }

    float* Cb = C + (size_t)(blockIdx.y * 256) * N + blockIdx.x * 128;
#pragma unroll
    for (int mt = 0; mt < 4; mt++) {
#pragma unroll
        for (int nt = 0; nt < 8; nt++) {
            int r = wr * 64 + mt * 16 + gid;
            int cc = wq * 64 + nt * 8 + tig * 2;
            *(float2*)(Cb + (size_t)r * N + cc) =
                make_float2(acc[mt][nt][0], acc[mt][nt][1]);
            *(float2*)(Cb + (size_t)(r + 8) * N + cc) =
                make_float2(acc[mt][nt][2], acc[mt][nt][3]);
        }
    }
}

__global__ __launch_bounds__(256, 1) void k_gemm_qkv() {
    gemm_packed_body(g_pA, g_pBq, g_qkv, 3072, 1024);
}
__global__ __launch_bounds__(256, 1) void k_gemm_out(float* __restrict__ out) {
    gemm_packed_body(g_pA, g_pBo, out, 1024, 1024);
}

// ---------------- qa: register-tiled sim GEMM + fused softmax over m ----------------
__global__ __launch_bounds__(256) void k_qa(const float* __restrict__ agent) {
    extern __shared__ float fsm[];
    float* Qs = fsm;          // [64k][128n]
    float* Ams = fsm + 8192;  // [64k][128m]
    const int b = blockIdx.z, h = blockIdx.y, n0 = blockIdx.x * 128;
    const int t = threadIdx.x;

    {
        int m = t >> 1, kb = (t & 1) * 32;
        const float4* src = (const float4*)(agent + h * 8192 + m * 64 + kb);
#pragma unroll
        for (int i = 0; i < 8; i++) {
            float4 v = src[i];
            int k = kb + i * 4;
            Ams[(k + 0) * 128 + m] = v.x * SCALE_A;
            Ams[(k + 1) * 128 + m] = v.y * SCALE_A;
            Ams[(k + 2) * 128 + m] = v.z * SCALE_A;
            Ams[(k + 3) * 128 + m] = v.w * SCALE_A;
        }
    }
    {
        int n = t >> 1, kb = (t & 1) * 32;
        const float4* src = (const float4*)(g_qkv + ((size_t)(b * 4096 + n0 + n)) * 3072 + h * 64 + kb);
#pragma unroll
        for (int i = 0; i < 8; i++) {
            float4 v = src[i];
            int k = kb + i * 4;
            Qs[(k + 0) * 128 + n] = v.x;
            Qs[(k + 1) * 128 + n] = v.y;
            Qs[(k + 2) * 128 + n] = v.z;
            Qs[(k + 3) * 128 + n] = v.w;
        }
    }
    __syncthreads();

    const int tx = t & 15, ty = t >> 4;
    float acc[8][8];
#pragma unroll
    for (int i = 0; i < 8; i++)
#pragma unroll
        for (int j = 0; j < 8; j++) acc[i][j] = 0.f;

#pragma unroll 4
    for (int kk = 0; kk < 64; kk++) {
        float4 q0 = *(const float4*)&Qs[kk * 128 + ty * 4];
        float4 q1 = *(const float4*)&Qs[kk * 128 + 64 + ty * 4];
        float4 a0 = *(const float4*)&Ams[kk * 128 + tx * 4];
        float4 a1 = *(const float4*)&Ams[kk * 128 + 64 + tx * 4];
        const float qn[8] = {q0.x, q0.y, q0.z, q0.w, q1.x, q1.y, q1.z, q1.w};
        const float am[8] = {a0.x, a0.y, a0.z, a0.w, a1.x, a1.y, a1.z, a1.w};
#pragma unroll
        for (int i = 0; i < 8; i++)
#pragma unroll
            for (int j = 0; j < 8; j++) acc[i][j] += qn[i] * am[j];
    }

    const size_t base = ((size_t)(b * 16 + h)) * 524288;
#pragma unroll
    for (int i = 0; i < 8; i++) {
        float mx = acc[i][0];
#pragma unroll
        for (int j = 1; j < 8; j++) mx = fmaxf(mx, acc[i][j]);
#pragma unroll
        for (int off = 8; off > 0; off >>= 1)
            mx = fmaxf(mx, __shfl_xor_sync(0xffffffffu, mx, off));
        float e[8], sum = 0.f;
#pragma unroll
        for (int j = 0; j < 8; j++) { e[j] = __expf(acc[i][j] - mx); sum += e[j]; }
#pragma unroll
        for (int off = 8; off > 0; off >>= 1)
            sum += __shfl_xor_sync(0xffffffffu, sum, off);
        const float inv = 1.f / sum;
        const int n_i = n0 + ((i < 4) ? (ty * 4 + i) : (64 + ty * 4 + i - 4));
        float* row = g_qa + base + (size_t)n_i * 128;
        *(float4*)(row + tx * 4) = make_float4(e[0] * inv, e[1] * inv, e[2] * inv, e[3] * inv);
        *(float4*)(row + 64 + tx * 4) = make_float4(e[4] * inv, e[5] * inv, e[6] * inv, e[7] * inv);
    }
}

// ---------------- ak: sim GEMM + fused PARTIAL softmax stats ----------------
__global__ __launch_bounds__(256) void k_ak_sim(const float* __restrict__ agent) {
    extern __shared__ float fsm[];
    float* Ks = fsm;          // [64k][128n]
    float* Ams = fsm + 8192;  // [64k][128m]
    const int b = blockIdx.z, h = blockIdx.y, n0 = blockIdx.x * 128;
    const int t = threadIdx.x;

    {
        int m = t >> 1, kb = (t & 1) * 32;
        const float4* src = (const float4*)(agent + h * 8192 + m * 64 + kb);
#pragma unroll
        for (int i = 0; i < 8; i++) {
            float4 v = src[i];
            int k = kb + i * 4;
            Ams[(k + 0) * 128 + m] = v.x * SCALE_A;
            Ams[(k + 1) * 128 + m] = v.y * SCALE_A;
            Ams[(k + 2) * 128 + m] = v.z * SCALE_A;
            Ams[(k + 3) * 128 + m] = v.w * SCALE_A;
        }
    }
    {
        int n = t >> 1, kb = (t & 1) * 32;
        const float4* src = (const float4*)(g_qkv + ((size_t)(b * 4096 + n0 + n)) * 3072 + 1024 + h * 64 + kb);
#pragma unroll
        for (int i = 0; i < 8; i++) {
            float4 v = src[i];
            int k = kb + i * 4;
            Ks[(k + 0) * 128 + n] = v.x;
            Ks[(k + 1) * 128 + n] = v.y;
            Ks[(k + 2) * 128 + n] = v.z;
            Ks[(k + 3) * 128 + n] = v.w;
        }
    }
    __syncthreads();

    const int tx = t & 15, ty = t >> 4;
    float acc[8][8];
#pragma unroll
    for (int i = 0; i < 8; i++)
#pragma unroll
        for (int j = 0; j < 8; j++) acc[i][j] = 0.f;

#pragma unroll 4
    for (int kk = 0; kk < 64; kk++) {
        float4 a0 = *(const float4*)&Ams[kk * 128 + ty * 4];
        float4 a1 = *(const float4*)&Ams[kk * 128 + 64 + ty * 4];
        float4 k0 = *(const float4*)&Ks[kk * 128 + tx * 4];
        float4 k1 = *(const float4*)&Ks[kk * 128 + 64 + tx * 4];
        const float am[8] = {a0.x, a0.y, a0.z, a0.w, a1.x, a1.y, a1.z, a1.w};
        const float kn[8] = {k0.x, k0.y, k0.z, k0.w, k1.x, k1.y, k1.z, k1.w};
#pragma unroll
        for (int i = 0; i < 8; i++)
#pragma unroll
            for (int j = 0; j < 8; j++) acc[i][j] += am[i] * kn[j];
    }

    const unsigned char* mrow = g_mask + b * 4096 + n0;
    bool mk[8];
#pragma unroll
    for (int j = 0; j < 4; j++) {
        mk[j] = mrow[tx * 4 + j] != 0;
        mk[4 + j] = mrow[64 + tx * 4 + j] != 0;
    }

    const size_t base = ((size_t)(b * 16 + h)) * 524288;
#pragma unroll
    for (int i = 0; i < 8; i++) {
        const int m_i = (i < 4) ? (ty * 4 + i) : (64 + ty * 4 + i - 4);
        float* row = g_ak + base + (size_t)m_i * 4096 + n0;
        *(float4*)(row + tx * 4) = make_float4(acc[i][0], acc[i][1], acc[i][2], acc[i][3]);
        *(float4*)(row + 64 + tx * 4) = make_float4(acc[i][4], acc[i][5], acc[i][6], acc[i][7]);

        // partial (max, sumexp) over this block's 128 n
        float mx = -3.402823e38f;
#pragma unroll
        for (int j = 0; j < 8; j++) mx = fmaxf(mx, mk[j] ? acc[i][j] : -3.402823e38f);
#pragma unroll
        for (int off = 8; off > 0; off >>= 1)
            mx = fmaxf(mx, __shfl_xor_sync(0xffffffffu, mx, off));
        float sm = 0.f;
#pragma unroll
        for (int j = 0; j < 8; j++) sm += mk[j] ? __expf(acc[i][j] - mx) : 0.f;
#pragma unroll
        for (int off = 8; off > 0; off >>= 1)
            sm += __shfl_xor_sync(0xffffffffu, sm, off);
        if (tx == 0)
            g_akpart[((size_t)((b * 16 + h) * 128 + m_i)) * 32 + blockIdx.x] =
                make_float2(mx, sm);
    }
}

// ---------------- combine partial stats -> g_akstat ----------------
__global__ __launch_bounds__(256) void k_ak_comb() {
    const int row = blockIdx.x * 256 + threadIdx.x;   // 8192 rows
    const float2* p = g_akpart + (size_t)row * 32;
    float mx = -3.402823e38f, sum = 0.f;
#pragma unroll 8
    for (int i = 0; i < 32; i++) {
        float2 q = p[i];
        float nm = fmaxf(mx, q.x);
        sum = sum * __expf(mx - nm) + q.y * __expf(q.x - nm);
        mx = nm;
    }
    g_akstat[row] = make_float2(mx, 1.f / sum);
}

// ---------------- talking-heads mixes (float4 vectorized) ----------------
__global__ __launch_bounds__(256) void k_mix_qa(const float* __restrict__ W) {
    __shared__ float Ws[256];
    Ws[threadIdx.x] = W[threadIdx.x];
    __syncthreads();
    const size_t S = 524288;
    const int b = blockIdx.y;
    const size_t s = ((size_t)blockIdx.x * 256 + threadIdx.x) * 4;
    float4 v[16];
#pragma unroll
    for (int h = 0; h < 16; h++)
        v[h] = *(const float4*)(g_qa + (size_t)(b * 16 + h) * S + s);
#pragma unroll
    for (int g = 0; g < 16; g++) {
        float4 o = make_float4(0.f, 0.f, 0.f, 0.f);
#pragma unroll
        for (int h = 0; h < 16; h++) {
            float w = Ws[g * 16 + h];
            o.x += w * v[h].x; o.y += w * v[h].y;
            o.z += w * v[h].z; o.w += w * v[h].w;
        }
        *(float4*)(g_qam + (size_t)(b * 16 + g) * S + s) = o;
    }
}

__global__ __launch_bounds__(256) void k_mix_ak(const float* __restrict__ W) {
    __shared__ float Ws[256];
    Ws[threadIdx.x] = W[threadIdx.x];
    __syncthreads();
    const size_t S = 524288;
    const int b = blockIdx.y;
    const size_t s = ((size_t)blockIdx.x * 256 + threadIdx.x) * 4;
    const int m = (int)(s >> 12);
    const int n = (int)(s & 4095);
    const uchar4 mk = *(const uchar4*)(g_mask + b * 4096 + n);
    float4 v[16];
#pragma unroll
    for (int h = 0; h < 16; h++) {
        float4 raw = *(const float4*)(g_ak + (size_t)(b * 16 + h) * S + s);
        float2 st = g_akstat[(b * 16 + h) * 128 + m];
        v[h].x = mk.x ? __expf(raw.x - st.x) * st.y : 0.f;
        v[h].y = mk.y ? __expf(raw.y - st.x) * st.y : 0.f;
        v[h].z = mk.z ? __expf(raw.z - st.x) * st.y : 0.f;
        v[h].w = mk.w ? __expf(raw.w - st.x) * st.y : 0.f;
    }
#pragma unroll
    for (int g = 0; g < 16; g++) {
        float4 o = make_float4(0.f, 0.f, 0.f, 0.f);
#pragma unroll
        for (int h = 0; h < 16; h++) {
            float w = Ws[g * 16 + h];
            o.x += w * v[h].x; o.y += w * v[h].y;
            o.z += w * v[h].z; o.w += w * v[h].w;
        }
        *(float4*)(g_akm + (size_t)(b * 16 + g) * S + s) = o;
    }
}

// ---------------- agent_out partials: split n into 4 ranges ----------------
__global__ __launch_bounds__(512) void k_agent_out() {
    __shared__ float akm_s[128 * 64];
    __shared__ float v_s[64 * 64];
    const int g = blockIdx.x, b = blockIdx.y, sp = blockIdx.z;
    const int t = threadIdx.x;
    const int d = t & 63, mg = t >> 6;
    const float* akm_b = g_akm + (size_t)(b * 16 + g) * 128 * 4096;
    const float* v_b = g_qkv + (size_t)b * 4096 * 3072 + 2048 + g * 64;

    float acc[16];
#pragma unroll
    for (int j = 0; j < 16; j++) acc[j] = 0.f;

    const int nlo = sp * 1024, nhi = nlo + 1024;
    for (int n0 = nlo; n0 < nhi; n0 += 64) {
#pragma unroll
        for (int i = 0; i < 16; i++) {
            int idx = t + i * 512;
            int r = idx >> 6, c = idx & 63;
            akm_s[idx] = akm_b[(size_t)r * 4096 + n0 + c];
        }
#pragma unroll
        for (int i = 0; i < 8; i++) {
            int idx = t + i * 512;
            int r = idx >> 6, c = idx & 63;
            v_s[idx] = v_b[(size_t)(n0 + r) * 3072 + c];
        }
        __syncthreads();
#pragma unroll 4
        for (int nn = 0; nn < 64; nn++) {
            float vv = v_s[nn * 64 + d];
#pragma unroll
            for (int j = 0; j < 16; j++)
                acc[j] += akm_s[(mg * 16 + j) * 64 + nn] * vv;
        }
        __syncthreads();
    }
    float* out = g_aop + (size_t)sp * 524288 + (size_t)(b * 16 + g) * 8192;
#pragma unroll
    for (int j = 0; j < 16; j++) out[(mg * 16 + j) * 64 + d] = acc[j];
}

__global__ __launch_bounds__(256) void k_ao_reduce() {
    const int i = blockIdx.x * 256 + threadIdx.x;     // float4 index, 131072 total
    const float4* p = (const float4*)g_aop;
    float4 a = p[i], bq = p[131072 + i], c = p[262144 + i], d = p[393216 + i];
    ((float4*)g_ao)[i] = make_float4(a.x + bq.x + c.x + d.x, a.y + bq.y + c.y + d.y,
                                     a.z + bq.z + c.z + d.z, a.w + bq.w + c.w + d.w);
}

// ---------------- out_pre: [b,n,g*64+d] = sum_m qam[b,g,n,m]*ao[b,g,m,d], masked ----
__global__ __launch_bounds__(256) void k_out_pre() {
    extern __shared__ float fsm[];
    float* qs = fsm;          // [64m][128n]
    float* aos = fsm + 8192;  // [128m][64d]
    const int n0 = blockIdx.x * 128, g = blockIdx.y, b = blockIdx.z;
    const int t = threadIdx.x;
    const int tx = t & 15, ty = t >> 4;
    const float* qam_b = g_qam + (size_t)(b * 16 + g) * 524288;
    const float* ao_b = g_ao + (size_t)(b * 16 + g) * 8192;

#pragma unroll
    for (int i = 0; i < 8; i++) {
        int f = t + i * 256;
        int m = f >> 4, df = (f & 15) * 4;
        *(float4*)&aos[m * 64 + df] = *(const float4*)(ao_b + m * 64 + df);
    }

    float acc[8][4];
#pragma unroll
    for (int i = 0; i < 8; i++)
#pragma unroll
        for (int w = 0; w < 4; w++) acc[i][w] = 0.f;

    for (int mc = 0; mc < 128; mc += 64) {
        __syncthreads();
#pragma unroll
        for (int i = 0; i < 8; i++) {
            int f = t + i * 256;
            int n = f >> 4, mf = (f & 15) * 4;
            float4 v = *(const float4*)(qam_b + (size_t)(n0 + n) * 128 + mc + mf);
            qs[(mf + 0) * 128 + n] = v.x;
            qs[(mf + 1) * 128 + n] = v.y;
            qs[(mf + 2) * 128 + n] = v.z;
            qs[(mf + 3) * 128 + n] = v.w;
        }
        __syncthreads();
#pragma unroll 4
        for (int mm = 0; mm < 64; mm++) {
            float4 r0 = *(const float4*)&qs[mm * 128 + ty * 4];
            float4 r1 = *(const float4*)&qs[mm * 128 + 64 + ty * 4];
            float4 rb = *(const float4*)&aos[(mc + mm) * 64 + tx * 4];
            const float rn[8] = {r0.x, r0.y, r0.z, r0.w, r1.x, r1.y, r1.z, r1.w};
            const float* bw = &rb.x;
#pragma unroll
            for (int i = 0; i < 8; i++)
#pragma unroll
                for (int w = 0; w < 4; w++) acc[i][w] += rn[i] * bw[w];
        }
    }

#pragma unroll
    for (int i = 0; i < 8; i++) {
        const int n_i = n0 + ((i < 4) ? (ty * 4 + i) : (64 + ty * 4 + i - 4));
        const float msk = g_mask[b * 4096 + n_i] ? 1.f : 0.f;
        *(float4*)(g_outpre + ((size_t)(b * 4096 + n_i)) * 1024 + g * 64 + tx * 4) =
            make_float4(acc[i][0] * msk, acc[i][1] * msk, acc[i][2] * msk, acc[i][3] * msk);
    }
}

// ---------------- launch ----------------
extern "C" void kernel_launch(void* const* d_in, const int* in_sizes, int n_in,
                              void* d_out, int out_size) {
    const float* x = (const float*)d_in[0];
    const void* mask_raw = d_in[1];
    const float* W_qkv = (const float*)d_in[2];
    const float* agent = (const float*)d_in[3];
    const float* W_qa = (const float*)d_in[4];
    const float* W_ak = (const float*)d_in[5];
    const float* W_out = (const float*)d_in[6];
    float* out = (float*)d_out;

    cudaFuncSetAttribute(k_gemm_qkv, cudaFuncAttributeMaxDynamicSharedMemorySize, G2_SMEM_BYTES);
    cudaFuncSetAttribute(k_gemm_out, cudaFuncAttributeMaxDynamicSharedMemorySize, G2_SMEM_BYTES);
    cudaFuncSetAttribute(k_qa, cudaFuncAttributeMaxDynamicSharedMemorySize, 65536);
    cudaFuncSetAttribute(k_ak_sim, cudaFuncAttributeMaxDynamicSharedMemorySize, 65536);
    cudaFuncSetAttribute(k_out_pre, cudaFuncAttributeMaxDynamicSharedMemorySize, 65536);

    // 0. mask canonicalization + operand packing (R9 pack kernels)
    k_mask_canon<<<1, 256>>>(mask_raw);
    k_packB_qkv<<<3072, 256>>>(W_qkv);
    k_packB_out<<<1024, 256>>>(W_out);
    k_packA_x<<<16384, 256>>>(x);
    // 1. qkv projection (R9 2-stage pipeline)
    k_gemm_qkv<<<dim3(3072 / 128, 16384 / 256), 256, G2_SMEM_BYTES>>>();
    // 2. qa similarities + fused softmax (over m) -> [b,h,n,m]
    k_qa<<<dim3(32, 16, 4), 256, 65536>>>(agent);
    // 3. ak similarities + fused partial softmax stats
    k_ak_sim<<<dim3(32, 16, 4), 256, 65536>>>(agent);
    // 4. combine partial stats (2MB read)
    k_ak_comb<<<32, 256>>>();
    // 5. talking heads (float4; ak mix applies softmax on the fly)
    k_mix_qa<<<dim3(512, 4), 256>>>(W_qa);
    k_mix_ak<<<dim3(512, 4), 256>>>(W_ak);
    // 6. agent_out = ak_mixed @ v (4-way n-split + reduce)
    k_agent_out<<<dim3(16, 4, 4), 512>>>();
    k_ao_reduce<<<512, 256>>>();
    // 7. out_pre = qam @ agent_out (+ output mask)
    k_out_pre<<<dim3(32, 16, 4), 256, 65536>>>();
    // 8. final projection (pack outpre, then packed GEMM)
    k_packA_outpre<<<16384, 256>>>();
    k_gemm_out<<<dim3(1024 / 128, 16384 / 256), 256, G2_SMEM_BYTES>>>(out);
}

// round 13
// speedup vs baseline: 1.1261x; 1.0304x over previous
#include <cuda_runtime.h>
#include <math.h>
#include <stdint.h>

// Problem constants
// B=4, N=4096, DIM=1024, HEADS=16, DIM_HEAD=64, M=128, DIM_INNER=1024
#define SCALE_A 0.125f   // 64^-0.5

// ---------------- scratch (device globals; no runtime allocation) ----------------
// RULE (learned R2, re-learned R8): device globals may ONLY be referenced from
// device code. Host-side symbol addresses are invalid (GB300 ATS makes it silent).
__device__ float g_qkv[50331648];    // [4,4096,3072]
__device__ float g_qa[33554432];     // qa_attn  [b,h,n,m]  (m fastest)
__device__ float g_qam[33554432];    // qa mixed [b,g,n,m]
__device__ float g_ak[33554432];     // ak raw sims [b,h,m,n] (n fastest)
__device__ float g_akm[33554432];    // ak mixed (softmaxed) [b,g,m,n]
__device__ float2 g_akstat[8192];    // per (b,h,m): {rowmax, 1/sumexp}
__device__ float g_ao[524288];       // agent_out [b,g,m=128,d=64]
__device__ float g_aop[2097152];     // agent_out partials [4 splits][b,g,m,d]
__device__ unsigned char g_mask[16384]; // canonical uint8 mask [b,n]
__device__ float g_pA[16777216];     // packed A (16384x1024), reused by both GEMMs
__device__ float g_pBq[3145728];     // packed W_qkv (1024x3072)
__device__ float g_pBo[1048576];     // packed W_out (1024x1024)

// ---------------- helpers ----------------
__device__ __forceinline__ unsigned f2tf32(float x) {
    unsigned r;
    asm("cvt.rna.tf32.f32 %0, %1;" : "=r"(r) : "f"(x));
    return r;
}
__device__ __forceinline__ uint32_t smem_u32(const void* p) {
    uint32_t a;
    asm("{ .reg .u64 t; cvta.to.shared.u64 t, %1; cvt.u32.u64 %0, t; }" : "=r"(a) : "l"(p));
    return a;
}
__device__ __forceinline__ void cp16(uint32_t saddr, const void* g) {
    asm volatile("cp.async.cg.shared.global [%0], [%1], 16;" :: "r"(saddr), "l"(g));
}
__device__ __forceinline__ void mma_tf32(float* c, const unsigned* a,
                                         unsigned b0, unsigned b1) {
    asm volatile(
        "mma.sync.aligned.m16n8k8.row.col.f32.tf32.tf32.f32 "
        "{%0,%1,%2,%3}, {%4,%5,%6,%7}, {%8,%9}, {%0,%1,%2,%3};"
        : "+f"(c[0]), "+f"(c[1]), "+f"(c[2]), "+f"(c[3])
        : "r"(a[0]), "r"(a[1]), "r"(a[2]), "r"(a[3]), "r"(b0), "r"(b1));
}

// ---------------- mask canonicalization ----------------
__global__ void k_mask_canon(const void* __restrict__ mraw) {
    __shared__ int notI32, notF32;
    if (threadIdx.x == 0) { notI32 = 0; notF32 = 0; }
    __syncthreads();
    const unsigned int* w = (const unsigned int*)mraw;
    int a = 0, b = 0;
    for (int i = threadIdx.x; i < 4096; i += 256) {
        unsigned int v = w[i];
        if (v > 1u) a = 1;
        if (v != 0u && v != 0x3F800000u) b = 1;
    }
    if (a) atomicOr(&notI32, 1);
    if (b) atomicOr(&notF32, 1);
    __syncthreads();
    const int mode = notI32 ? (notF32 ? 2 : 1) : 0;
    for (int i = threadIdx.x; i < 16384; i += 256) {
        unsigned char mv;
        if (mode == 0)      mv = (((const int*)mraw)[i] != 0);
        else if (mode == 1) mv = (((const float*)mraw)[i] != 0.0f);
        else                mv = (((const unsigned char*)mraw)[i] != 0);
        g_mask[i] = mv;
    }
}

// ---------------- operand pack bodies (R9 versions — known good) ----------------
// A layout: for row r, col k (K cols):
//   rowtile=r>>8, blk=(r>>4)&15, gidE=r&7, hb=(r>>3)&1
//   c=k>>5, ks=(k>>3)&3, tig=k&3, hi=(k>>2)&1
//   lane=(gidE*4+tig)^ks, j=hi*2+hb
//   idx = (rowtile*(K/32)+c)*8192 + ((blk*4+ks)*32+lane)*4 + j
__device__ __forceinline__ void packA_body(const float* __restrict__ src,
                                           float* __restrict__ dst, int K) {
    const size_t t = (size_t)blockIdx.x * 256 + threadIdx.x;
    const int kq = K >> 2;
    const int r = (int)(t / kq);
    const int k4 = (int)(t % kq) * 4;
    float4 v = *(const float4*)(src + (size_t)r * K + k4);
    const int nc = K >> 5;
    const int rowtile = r >> 8, blk = (r >> 4) & 15, gidE = r & 7, hb = (r >> 3) & 1;
    float* base = dst + (size_t)rowtile * nc * 8192;
    const float vv[4] = {v.x, v.y, v.z, v.w};
#pragma unroll
    for (int e = 0; e < 4; e++) {
        int k = k4 + e;
        int c = k >> 5, ks = (k >> 3) & 3, tig = k & 3, hi = (k >> 2) & 1;
        int lane = (gidE * 4 + tig) ^ ks;
        int j = hi * 2 + hb;
        base[(size_t)c * 8192 + ((blk * 4 + ks) * 32 + lane) * 4 + j] =
            __uint_as_float(f2tf32(vv[e]));
    }
}

// B layout: W[k][n] row-major (K x N):
//   coltile=n>>7, nblk=(n>>3)&15, gidE=n&7
//   c=k>>5, ks=(k>>3)&3, tig=k&3, v=(k>>2)&1
//   lane=(gidE*4+tig)^nblk
//   idx = (coltile*(K/32)+c)*4096 + ((nblk*4+ks)*32+lane)*2 + v
__device__ __forceinline__ void packB_body(const float* __restrict__ src,
                                           float* __restrict__ dst, int N, int K) {
    const size_t t = (size_t)blockIdx.x * 256 + threadIdx.x;
    const int nq = N >> 2;
    const int k = (int)(t / nq);
    const int n4 = (int)(t % nq) * 4;
    float4 v = *(const float4*)(src + (size_t)k * N + n4);
    const int nc = K >> 5;
    const int c = k >> 5, ks = (k >> 3) & 3, tig = k & 3, vb = (k >> 2) & 1;
    const float vv[4] = {v.x, v.y, v.z, v.w};
#pragma unroll
    for (int e = 0; e < 4; e++) {
        int n = n4 + e;
        int coltile = n >> 7, nblk = (n >> 3) & 15, gidE = n & 7;
        int lane = (gidE * 4 + tig) ^ nblk;
        dst[((size_t)coltile * nc + c) * 4096 + ((nblk * 4 + ks) * 32 + lane) * 2 + vb] =
            __uint_as_float(f2tf32(vv[e]));
    }
}

// Wrappers: device globals bound in DEVICE code.
__global__ __launch_bounds__(256) void k_packA_x(const float* __restrict__ x) {
    packA_body(x, g_pA, 1024);
}
__global__ __launch_bounds__(256) void k_packB_qkv(const float* __restrict__ w) {
    packB_body(w, g_pBq, 3072, 1024);
}
__global__ __launch_bounds__(256) void k_packB_out(const float* __restrict__ w) {
    packB_body(w, g_pBo, 1024, 1024);
}

// ---------------- packed tf32 GEMM (R9 2-stage version — known good) ----------------
// CTA 256m x 128n, 8 warps (4m x 2n), warp tile 64x64, BK=32, cp.async double-buffer.
#define G2_STAGE_WORDS 12288          // A 8192 + B 4096
#define G2_SMEM_BYTES (2 * G2_STAGE_WORDS * 4)   // 98304

__device__ __forceinline__ void gemm_packed_body(const float* __restrict__ gA,
                                                 const float* __restrict__ gB,
                                                 float* __restrict__ C,
                                                 int N, int K) {
    extern __shared__ unsigned dsm[];
    unsigned* buf0 = dsm;
    unsigned* buf1 = dsm + G2_STAGE_WORDS;

    const int tid = threadIdx.x;
    const int warp = tid >> 5, lane = tid & 31;
    const int gid = lane >> 2, tig = lane & 3;
    const int wr = warp & 3, wq = warp >> 2;
    const int nc = K >> 5;

    const char* Asrc = (const char*)(gA + (size_t)blockIdx.y * nc * 8192);
    const char* Bsrc = (const char*)(gB + (size_t)blockIdx.x * nc * 4096);
    const uint32_t sA0 = smem_u32(buf0);
    const uint32_t sA1 = smem_u32(buf1);

    float acc[4][8][4];
#pragma unroll
    for (int i = 0; i < 4; i++)
#pragma unroll
        for (int j = 0; j < 8; j++)
#pragma unroll
            for (int l = 0; l < 4; l++) acc[i][j][l] = 0.f;

    auto issue = [&](uint32_t sbuf, int c) {
        const char* a = Asrc + (size_t)c * 32768;
        const char* b = Bsrc + (size_t)c * 16384;
#pragma unroll
        for (int i = 0; i < 8; i++) {
            int off = (tid + i * 256) * 16;
            cp16(sbuf + off, a + off);
        }
#pragma unroll
        for (int i = 0; i < 4; i++) {
            int off = (tid + i * 256) * 16;
            cp16(sbuf + 32768 + off, b + off);
        }
    };

    issue(sA0, 0);
    asm volatile("cp.async.commit_group;" ::: "memory");

    for (int c = 0; c < nc; c++) {
        const int cur = c & 1;
        if (c + 1 < nc) {
            issue(cur ? sA0 : sA1, c + 1);
            asm volatile("cp.async.commit_group;" ::: "memory");
            asm volatile("cp.async.wait_group 1;" ::: "memory");
        } else {
            asm volatile("cp.async.wait_group 0;" ::: "memory");
        }
        __syncthreads();
        const unsigned* Ap = cur ? buf1 : buf0;
        const unsigned* Bp = Ap + 8192;
#pragma unroll
        for (int ks = 0; ks < 4; ks++) {
            uint4 a[4];
#pragma unroll
            for (int mt = 0; mt < 4; mt++)
                a[mt] = *(const uint4*)&Ap[(((wr * 4 + mt) * 4 + ks) * 32 + (lane ^ ks)) * 4];
#pragma unroll
            for (int nt = 0; nt < 8; nt++) {
                int nblk = wq * 8 + nt;
                uint2 bb = *(const uint2*)&Bp[((nblk * 4 + ks) * 32 + (lane ^ nblk)) * 2];
#pragma unroll
                for (int mt = 0; mt < 4; mt++)
                    mma_tf32(acc[mt][nt], (const unsigned*)&a[mt], bb.x, bb.y);
            }
        }
        __syncthreads();
    }

    float* Cb = C + (size_t)(blockIdx.y * 256) * N + blockIdx.x * 128;
#pragma unroll
    for (int mt = 0; mt < 4; mt++) {
#pragma unroll
        for (int nt = 0; nt < 8; nt++) {
            int r = wr * 64 + mt * 16 + gid;
            int cc = wq * 64 + nt * 8 + tig * 2;
            *(float2*)(Cb + (size_t)r * N + cc) =
                make_float2(acc[mt][nt][0], acc[mt][nt][1]);
            *(float2*)(Cb + (size_t)(r + 8) * N + cc) =
                make_float2(acc[mt][nt][2], acc[mt][nt][3]);
        }
    }
}

__global__ __launch_bounds__(256, 1) void k_gemm_qkv() {
    gemm_packed_body(g_pA, g_pBq, g_qkv, 3072, 1024);
}
__global__ __launch_bounds__(256, 1) void k_gemm_out(float* __restrict__ out) {
    gemm_packed_body(g_pA, g_pBo, out, 1024, 1024);
}

// ---------------- qa: register-tiled sim GEMM + fused softmax over m ----------------
__global__ __launch_bounds__(256) void k_qa(const float* __restrict__ agent) {
    extern __shared__ float fsm[];
    float* Qs = fsm;          // [64k][128n]
    float* Ams = fsm + 8192;  // [64k][128m]
    const int b = blockIdx.z, h = blockIdx.y, n0 = blockIdx.x * 128;
    const int t = threadIdx.x;

    {
        int m = t >> 1, kb = (t & 1) * 32;
        const float4* src = (const float4*)(agent + h * 8192 + m * 64 + kb);
#pragma unroll
        for (int i = 0; i < 8; i++) {
            float4 v = src[i];
            int k = kb + i * 4;
            Ams[(k + 0) * 128 + m] = v.x * SCALE_A;
            Ams[(k + 1) * 128 + m] = v.y * SCALE_A;
            Ams[(k + 2) * 128 + m] = v.z * SCALE_A;
            Ams[(k + 3) * 128 + m] = v.w * SCALE_A;
        }
    }
    {
        int n = t >> 1, kb = (t & 1) * 32;
        const float4* src = (const float4*)(g_qkv + ((size_t)(b * 4096 + n0 + n)) * 3072 + h * 64 + kb);
#pragma unroll
        for (int i = 0; i < 8; i++) {
            float4 v = src[i];
            int k = kb + i * 4;
            Qs[(k + 0) * 128 + n] = v.x;
            Qs[(k + 1) * 128 + n] = v.y;
            Qs[(k + 2) * 128 + n] = v.z;
            Qs[(k + 3) * 128 + n] = v.w;
        }
    }
    __syncthreads();

    const int tx = t & 15, ty = t >> 4;
    float acc[8][8];
#pragma unroll
    for (int i = 0; i < 8; i++)
#pragma unroll
        for (int j = 0; j < 8; j++) acc[i][j] = 0.f;

#pragma unroll 4
    for (int kk = 0; kk < 64; kk++) {
        float4 q0 = *(const float4*)&Qs[kk * 128 + ty * 4];
        float4 q1 = *(const float4*)&Qs[kk * 128 + 64 + ty * 4];
        float4 a0 = *(const float4*)&Ams[kk * 128 + tx * 4];
        float4 a1 = *(const float4*)&Ams[kk * 128 + 64 + tx * 4];
        const float qn[8] = {q0.x, q0.y, q0.z, q0.w, q1.x, q1.y, q1.z, q1.w};
        const float am[8] = {a0.x, a0.y, a0.z, a0.w, a1.x, a1.y, a1.z, a1.w};
#pragma unroll
        for (int i = 0; i < 8; i++)
#pragma unroll
            for (int j = 0; j < 8; j++) acc[i][j] += qn[i] * am[j];
    }

    const size_t base = ((size_t)(b * 16 + h)) * 524288;
#pragma unroll
    for (int i = 0; i < 8; i++) {
        float mx = acc[i][0];
#pragma unroll
        for (int j = 1; j < 8; j++) mx = fmaxf(mx, acc[i][j]);
#pragma unroll
        for (int off = 8; off > 0; off >>= 1)
            mx = fmaxf(mx, __shfl_xor_sync(0xffffffffu, mx, off));
        float e[8], sum = 0.f;
#pragma unroll
        for (int j = 0; j < 8; j++) { e[j] = __expf(acc[i][j] - mx); sum += e[j]; }
#pragma unroll
        for (int off = 8; off > 0; off >>= 1)
            sum += __shfl_xor_sync(0xffffffffu, sum, off);
        const float inv = 1.f / sum;
        const int n_i = n0 + ((i < 4) ? (ty * 4 + i) : (64 + ty * 4 + i - 4));
        float* row = g_qa + base + (size_t)n_i * 128;
        *(float4*)(row + tx * 4) = make_float4(e[0] * inv, e[1] * inv, e[2] * inv, e[3] * inv);
        *(float4*)(row + 64 + tx * 4) = make_float4(e[4] * inv, e[5] * inv, e[6] * inv, e[7] * inv);
    }
}

// ---------------- ak: register-tiled sim GEMM, raw sims [b,h,m,n] ----------------
__global__ __launch_bounds__(256) void k_ak_sim(const float* __restrict__ agent) {
    extern __shared__ float fsm[];
    float* Ks = fsm;          // [64k][128n]
    float* Ams = fsm + 8192;  // [64k][128m]
    const int b = blockIdx.z, h = blockIdx.y, n0 = blockIdx.x * 128;
    const int t = threadIdx.x;

    {
        int m = t >> 1, kb = (t & 1) * 32;
        const float4* src = (const float4*)(agent + h * 8192 + m * 64 + kb);
#pragma unroll
        for (int i = 0; i < 8; i++) {
            float4 v = src[i];
            int k = kb + i * 4;
            Ams[(k + 0) * 128 + m] = v.x * SCALE_A;
            Ams[(k + 1) * 128 + m] = v.y * SCALE_A;
            Ams[(k + 2) * 128 + m] = v.z * SCALE_A;
            Ams[(k + 3) * 128 + m] = v.w * SCALE_A;
        }
    }
    {
        int n = t >> 1, kb = (t & 1) * 32;
        const float4* src = (const float4*)(g_qkv + ((size_t)(b * 4096 + n0 + n)) * 3072 + 1024 + h * 64 + kb);
#pragma unroll
        for (int i = 0; i < 8; i++) {
            float4 v = src[i];
            int k = kb + i * 4;
            Ks[(k + 0) * 128 + n] = v.x;
            Ks[(k + 1) * 128 + n] = v.y;
            Ks[(k + 2) * 128 + n] = v.z;
            Ks[(k + 3) * 128 + n] = v.w;
        }
    }
    __syncthreads();

    const int tx = t & 15, ty = t >> 4;
    float acc[8][8];
#pragma unroll
    for (int i = 0; i < 8; i++)
#pragma unroll
        for (int j = 0; j < 8; j++) acc[i][j] = 0.f;

#pragma unroll 4
    for (int kk = 0; kk < 64; kk++) {
        float4 a0 = *(const float4*)&Ams[kk * 128 + ty * 4];
        float4 a1 = *(const float4*)&Ams[kk * 128 + 64 + ty * 4];
        float4 k0 = *(const float4*)&Ks[kk * 128 + tx * 4];
        float4 k1 = *(const float4*)&Ks[kk * 128 + 64 + tx * 4];
        const float am[8] = {a0.x, a0.y, a0.z, a0.w, a1.x, a1.y, a1.z, a1.w};
        const float kn[8] = {k0.x, k0.y, k0.z, k0.w, k1.x, k1.y, k1.z, k1.w};
#pragma unroll
        for (int i = 0; i < 8; i++)
#pragma unroll
            for (int j = 0; j < 8; j++) acc[i][j] += am[i] * kn[j];
    }

    const size_t base = ((size_t)(b * 16 + h)) * 524288;
#pragma unroll
    for (int i = 0; i < 8; i++) {
        const int m_i = (i < 4) ? (ty * 4 + i) : (64 + ty * 4 + i - 4);
        float* row = g_ak + base + (size_t)m_i * 4096 + n0;
        *(float4*)(row + tx * 4) = make_float4(acc[i][0], acc[i][1], acc[i][2], acc[i][3]);
        *(float4*)(row + 64 + tx * 4) = make_float4(acc[i][4], acc[i][5], acc[i][6], acc[i][7]);
    }
}

// ---------------- ak row stats: max + 1/sumexp per (b,h,m), masked ----------------
__global__ __launch_bounds__(256) void k_ak_stats() {
    const int bhm = blockIdx.x;
    const int b = bhm >> 11;
    const float* row = g_ak + (size_t)bhm * 4096;
    const unsigned char* mrow = g_mask + b * 4096;
    const int t = threadIdx.x;

    float v[16];
    float mx = -3.402823e38f;
#pragma unroll
    for (int i = 0; i < 16; i++) {
        int n = t + i * 256;
        float xv = row[n];
        xv = mrow[n] ? xv : -3.402823e38f;
        v[i] = xv;
        mx = fmaxf(mx, xv);
    }
    __shared__ float red[256];
    red[t] = mx; __syncthreads();
    for (int s = 128; s > 0; s >>= 1) {
        if (t < s) red[t] = fmaxf(red[t], red[t + s]);
        __syncthreads();
    }
    mx = red[0]; __syncthreads();

    float sum = 0.f;
#pragma unroll
    for (int i = 0; i < 16; i++) sum += __expf(v[i] - mx);
    red[t] = sum; __syncthreads();
    for (int s = 128; s > 0; s >>= 1) {
        if (t < s) red[t] += red[t + s];
        __syncthreads();
    }
    if (t == 0) g_akstat[bhm] = make_float2(mx, 1.f / red[0]);
}

// ---------------- talking-heads mixes (R9 scalar versions — known good) ----------------
__global__ __launch_bounds__(256) void k_mix_qa(const float* __restrict__ W) {
    __shared__ float Ws[256];
    Ws[threadIdx.x] = W[threadIdx.x];
    __syncthreads();
    const size_t S = 524288;
    const int b = blockIdx.y;
    const size_t s = (size_t)blockIdx.x * 256 + threadIdx.x;
    float v[16];
#pragma unroll
    for (int h = 0; h < 16; h++) v[h] = g_qa[(size_t)(b * 16 + h) * S + s];
#pragma unroll
    for (int g = 0; g < 16; g++) {
        float o = 0.f;
#pragma unroll
        for (int h = 0; h < 16; h++) o += Ws[g * 16 + h] * v[h];
        g_qam[(size_t)(b * 16 + g) * S + s] = o;
    }
}

__global__ __launch_bounds__(256) void k_mix_ak(const float* __restrict__ W) {
    __shared__ float Ws[256];
    Ws[threadIdx.x] = W[threadIdx.x];
    __syncthreads();
    const size_t S = 524288;
    const int b = blockIdx.y;
    const size_t s = (size_t)blockIdx.x * 256 + threadIdx.x;
    const int m = (int)(s >> 12);
    const int n = (int)(s & 4095);
    const unsigned char msk = g_mask[b * 4096 + n];
    float v[16];
#pragma unroll
    for (int h = 0; h < 16; h++) {
        float raw = g_ak[(size_t)(b * 16 + h) * S + s];
        float2 st = g_akstat[(b * 16 + h) * 128 + m];
        v[h] = msk ? __expf(raw - st.x) * st.y : 0.f;
    }
#pragma unroll
    for (int g = 0; g < 16; g++) {
        float o = 0.f;
#pragma unroll
        for (int h = 0; h < 16; h++) o += Ws[g * 16 + h] * v[h];
        g_akm[(size_t)(b * 16 + g) * S + s] = o;
    }
}

// ---------------- agent_out partials: split n into 4 ranges ----------------
__global__ __launch_bounds__(512) void k_agent_out() {
    __shared__ float akm_s[128 * 64];
    __shared__ float v_s[64 * 64];
    const int g = blockIdx.x, b = blockIdx.y, sp = blockIdx.z;
    const int t = threadIdx.x;
    const int d = t & 63, mg = t >> 6;
    const float* akm_b = g_akm + (size_t)(b * 16 + g) * 128 * 4096;
    const float* v_b = g_qkv + (size_t)b * 4096 * 3072 + 2048 + g * 64;

    float acc[16];
#pragma unroll
    for (int j = 0; j < 16; j++) acc[j] = 0.f;

    const int nlo = sp * 1024, nhi = nlo + 1024;
    for (int n0 = nlo; n0 < nhi; n0 += 64) {
#pragma unroll
        for (int i = 0; i < 16; i++) {
            int idx = t + i * 512;
            int r = idx >> 6, c = idx & 63;
            akm_s[idx] = akm_b[(size_t)r * 4096 + n0 + c];
        }
#pragma unroll
        for (int i = 0; i < 8; i++) {
            int idx = t + i * 512;
            int r = idx >> 6, c = idx & 63;
            v_s[idx] = v_b[(size_t)(n0 + r) * 3072 + c];
        }
        __syncthreads();
#pragma unroll 4
        for (int nn = 0; nn < 64; nn++) {
            float vv = v_s[nn * 64 + d];
#pragma unroll
            for (int j = 0; j < 16; j++)
                acc[j] += akm_s[(mg * 16 + j) * 64 + nn] * vv;
        }
        __syncthreads();
    }
    float* out = g_aop + (size_t)sp * 524288 + (size_t)(b * 16 + g) * 8192;
#pragma unroll
    for (int j = 0; j < 16; j++) out[(mg * 16 + j) * 64 + d] = acc[j];
}

__global__ __launch_bounds__(256) void k_ao_reduce() {
    const int i = blockIdx.x * 256 + threadIdx.x;
    g_ao[i] = g_aop[i] + g_aop[524288 + i] + g_aop[1048576 + i] + g_aop[1572864 + i];
}

// ---------------- out_pre FUSED with packed-A epilogue ----------------
// Computes out_pre[b,n,g*64+d] = sum_m qam[b,g,n,m]*ao[b,g,m,d], applies mask,
// and writes DIRECTLY into packed-A layout (tf32-rounded) for the final GEMM.
// Packed-A coords: r = b*4096 + n_i, k = g*64 + tx*4 + w (K=1024, nc=32).
__global__ __launch_bounds__(256) void k_out_pre() {
    extern __shared__ float fsm[];
    float* qs = fsm;          // [64m][128n]
    float* aos = fsm + 8192;  // [128m][64d]
    const int n0 = blockIdx.x * 128, g = blockIdx.y, b = blockIdx.z;
    const int t = threadIdx.x;
    const int tx = t & 15, ty = t >> 4;
    const float* qam_b = g_qam + (size_t)(b * 16 + g) * 524288;
    const float* ao_b = g_ao + (size_t)(b * 16 + g) * 8192;

#pragma unroll
    for (int i = 0; i < 8; i++) {
        int f = t + i * 256;
        int m = f >> 4, df = (f & 15) * 4;
        *(float4*)&aos[m * 64 + df] = *(const float4*)(ao_b + m * 64 + df);
    }

    float acc[8][4];
#pragma unroll
    for (int i = 0; i < 8; i++)
#pragma unroll
        for (int w = 0; w < 4; w++) acc[i][w] = 0.f;

    for (int mc = 0; mc < 128; mc += 64) {
        __syncthreads();
#pragma unroll
        for (int i = 0; i < 8; i++) {
            int f = t + i * 256;
            int n = f >> 4, mf = (f & 15) * 4;
            float4 v = *(const float4*)(qam_b + (size_t)(n0 + n) * 128 + mc + mf);
            qs[(mf + 0) * 128 + n] = v.x;
            qs[(mf + 1) * 128 + n] = v.y;
            qs[(mf + 2) * 128 + n] = v.z;
            qs[(mf + 3) * 128 + n] = v.w;
        }
        __syncthreads();
#pragma unroll 4
        for (int mm = 0; mm < 64; mm++) {
            float4 r0 = *(const float4*)&qs[mm * 128 + ty * 4];
            float4 r1 = *(const float4*)&qs[mm * 128 + 64 + ty * 4];
            float4 rb = *(const float4*)&aos[(mc + mm) * 64 + tx * 4];
            const float rn[8] = {r0.x, r0.y, r0.z, r0.w, r1.x, r1.y, r1.z, r1.w};
            const float* bw = &rb.x;
#pragma unroll
            for (int i = 0; i < 8; i++)
#pragma unroll
                for (int w = 0; w < 4; w++) acc[i][w] += rn[i] * bw[w];
        }
    }

    // fused packed-A store: k = g*64 + tx*4 + w -> (c, ks, hi) fixed, tig = w
    const int kbase = g * 64 + tx * 4;
    const int kc = kbase >> 5;
    const int ks = (kbase >> 3) & 3;
    const int hi = (kbase >> 2) & 1;
#pragma unroll
    for (int i = 0; i < 8; i++) {
        const int n_i = n0 + ((i < 4) ? (ty * 4 + i) : (64 + ty * 4 + i - 4));
        const float msk = g_mask[b * 4096 + n_i] ? 1.f : 0.f;
        const int r = b * 4096 + n_i;
        const int rowtile = r >> 8, blk = (r >> 4) & 15, gidE = r & 7, hb = (r >> 3) & 1;
        const int j = hi * 2 + hb;
        float* base = g_pA + ((size_t)rowtile * 32 + kc) * 8192;
#pragma unroll
        for (int w = 0; w < 4; w++) {
            const int lane = (gidE * 4 + w) ^ ks;
            base[((blk * 4 + ks) * 32 + lane) * 4 + j] =
                __uint_as_float(f2tf32(acc[i][w] * msk));
        }
    }
}

// ---------------- launch ----------------
extern "C" void kernel_launch(void* const* d_in, const int* in_sizes, int n_in,
                              void* d_out, int out_size) {
    const float* x = (const float*)d_in[0];
    const void* mask_raw = d_in[1];
    const float* W_qkv = (const float*)d_in[2];
    const float* agent = (const float*)d_in[3];
    const float* W_qa = (const float*)d_in[4];
    const float* W_ak = (const float*)d_in[5];
    const float* W_out = (const float*)d_in[6];
    float* out = (float*)d_out;

    cudaFuncSetAttribute(k_gemm_qkv, cudaFuncAttributeMaxDynamicSharedMemorySize, G2_SMEM_BYTES);
    cudaFuncSetAttribute(k_gemm_out, cudaFuncAttributeMaxDynamicSharedMemorySize, G2_SMEM_BYTES);
    cudaFuncSetAttribute(k_qa, cudaFuncAttributeMaxDynamicSharedMemorySize, 65536);
    cudaFuncSetAttribute(k_ak_sim, cudaFuncAttributeMaxDynamicSharedMemorySize, 65536);
    cudaFuncSetAttribute(k_out_pre, cudaFuncAttributeMaxDynamicSharedMemorySize, 65536);

    // 0. mask canonicalization + operand packing
    k_mask_canon<<<1, 256>>>(mask_raw);
    k_packB_qkv<<<3072, 256>>>(W_qkv);
    k_packB_out<<<1024, 256>>>(W_out);
    k_packA_x<<<16384, 256>>>(x);
    // 1. qkv projection
    k_gemm_qkv<<<dim3(3072 / 128, 16384 / 256), 256, G2_SMEM_BYTES>>>();
    // 2. qa similarities + fused softmax (over m) -> [b,h,n,m]
    k_qa<<<dim3(32, 16, 4), 256, 65536>>>(agent);
    // 3. ak similarities (raw) -> [b,h,m,n]
    k_ak_sim<<<dim3(32, 16, 4), 256, 65536>>>(agent);
    // 4. ak row stats (masked max + 1/sumexp)
    k_ak_stats<<<8192, 256>>>();
    // 5. talking heads (ak mix applies softmax on the fly)
    k_mix_qa<<<dim3(2048, 4), 256>>>(W_qa);
    k_mix_ak<<<dim3(2048, 4), 256>>>(W_ak);
    // 6. agent_out = ak_mixed @ v (4-way n-split + reduce)
    k_agent_out<<<dim3(16, 4, 4), 512>>>();
    k_ao_reduce<<<2048, 256>>>();
    // 7. out_pre (+mask) written DIRECTLY in packed-A layout
    k_out_pre<<<dim3(32, 16, 4), 256, 65536>>>();
    // 8. final projection (no separate pack pass)
    k_gemm_out<<<dim3(1024 / 128, 16384 / 256), 256, G2_SMEM_BYTES>>>(out);
}

// round 14
// speedup vs baseline: 1.1667x; 1.0360x over previous
#include <cuda_runtime.h>
#include <cuda_bf16.h>
#include <math.h>
#include <stdint.h>

// Problem constants
// B=4, N=4096, DIM=1024, HEADS=16, DIM_HEAD=64, M=128, DIM_INNER=1024
#define SCALE_A 0.125f   // 64^-0.5

// ---------------- scratch (device globals; no runtime allocation) ----------------
// RULE (learned R2, re-learned R8): device globals may ONLY be referenced from
// device code. Host-side symbol addresses are invalid (GB300 ATS makes it silent).
__device__ float g_qkv[50331648];            // [4,4096,3072] fp32
__device__ __nv_bfloat16 g_qa[33554432];     // qa_attn  [b,h,n,m]  bf16
__device__ __nv_bfloat16 g_qam[33554432];    // qa mixed [b,g,n,m]  bf16
__device__ __nv_bfloat16 g_ak[33554432];     // ak raw sims [b,h,m,n] bf16
__device__ __nv_bfloat16 g_akm[33554432];    // ak mixed (softmaxed) [b,g,m,n] bf16
__device__ float2 g_akstat[8192];    // per (b,h,m): {rowmax, 1/sumexp}
__device__ float g_ao[524288];       // agent_out [b,g,m=128,d=64]
__device__ float g_aop[2097152];     // agent_out partials [4 splits][b,g,m,d]
__device__ unsigned char g_mask[16384]; // canonical uint8 mask [b,n]
__device__ float g_pA[16777216];     // packed A (16384x1024), reused by both GEMMs
__device__ float g_pBq[3145728];     // packed W_qkv (1024x3072)
__device__ float g_pBo[1048576];     // packed W_out (1024x1024)

// ---------------- helpers ----------------
__device__ __forceinline__ unsigned f2tf32(float x) {
    unsigned r;
    asm("cvt.rna.tf32.f32 %0, %1;" : "=r"(r) : "f"(x));
    return r;
}
__device__ __forceinline__ uint32_t smem_u32(const void* p) {
    uint32_t a;
    asm("{ .reg .u64 t; cvta.to.shared.u64 t, %1; cvt.u32.u64 %0, t; }" : "=r"(a) : "l"(p));
    return a;
}
__device__ __forceinline__ void cp16(uint32_t saddr, const void* g) {
    asm volatile("cp.async.cg.shared.global [%0], [%1], 16;" :: "r"(saddr), "l"(g));
}
__device__ __forceinline__ void mma_tf32(float* c, const unsigned* a,
                                         unsigned b0, unsigned b1) {
    asm volatile(
        "mma.sync.aligned.m16n8k8.row.col.f32.tf32.tf32.f32 "
        "{%0,%1,%2,%3}, {%4,%5,%6,%7}, {%8,%9}, {%0,%1,%2,%3};"
        : "+f"(c[0]), "+f"(c[1]), "+f"(c[2]), "+f"(c[3])
        : "r"(a[0]), "r"(a[1]), "r"(a[2]), "r"(a[3]), "r"(b0), "r"(b1));
}
__device__ __forceinline__ float2 bf2f(__nv_bfloat162 v) { return __bfloat1622float2(v); }

// ---------------- mask canonicalization ----------------
__global__ void k_mask_canon(const void* __restrict__ mraw) {
    __shared__ int notI32, notF32;
    if (threadIdx.x == 0) { notI32 = 0; notF32 = 0; }
    __syncthreads();
    const unsigned int* w = (const unsigned int*)mraw;
    int a = 0, b = 0;
    for (int i = threadIdx.x; i < 4096; i += 256) {
        unsigned int v = w[i];
        if (v > 1u) a = 1;
        if (v != 0u && v != 0x3F800000u) b = 1;
    }
    if (a) atomicOr(&notI32, 1);
    if (b) atomicOr(&notF32, 1);
    __syncthreads();
    const int mode = notI32 ? (notF32 ? 2 : 1) : 0;
    for (int i = threadIdx.x; i < 16384; i += 256) {
        unsigned char mv;
        if (mode == 0)      mv = (((const int*)mraw)[i] != 0);
        else if (mode == 1) mv = (((const float*)mraw)[i] != 0.0f);
        else                mv = (((const unsigned char*)mraw)[i] != 0);
        g_mask[i] = mv;
    }
}

// ---------------- operand pack bodies (R9 versions — known good) ----------------
__device__ __forceinline__ void packA_body(const float* __restrict__ src,
                                           float* __restrict__ dst, int K) {
    const size_t t = (size_t)blockIdx.x * 256 + threadIdx.x;
    const int kq = K >> 2;
    const int r = (int)(t / kq);
    const int k4 = (int)(t % kq) * 4;
    float4 v = *(const float4*)(src + (size_t)r * K + k4);
    const int nc = K >> 5;
    const int rowtile = r >> 8, blk = (r >> 4) & 15, gidE = r & 7, hb = (r >> 3) & 1;
    float* base = dst + (size_t)rowtile * nc * 8192;
    const float vv[4] = {v.x, v.y, v.z, v.w};
#pragma unroll
    for (int e = 0; e < 4; e++) {
        int k = k4 + e;
        int c = k >> 5, ks = (k >> 3) & 3, tig = k & 3, hi = (k >> 2) & 1;
        int lane = (gidE * 4 + tig) ^ ks;
        int j = hi * 2 + hb;
        base[(size_t)c * 8192 + ((blk * 4 + ks) * 32 + lane) * 4 + j] =
            __uint_as_float(f2tf32(vv[e]));
    }
}

__device__ __forceinline__ void packB_body(const float* __restrict__ src,
                                           float* __restrict__ dst, int N, int K) {
    const size_t t = (size_t)blockIdx.x * 256 + threadIdx.x;
    const int nq = N >> 2;
    const int k = (int)(t / nq);
    const int n4 = (int)(t % nq) * 4;
    float4 v = *(const float4*)(src + (size_t)k * N + n4);
    const int nc = K >> 5;
    const int c = k >> 5, ks = (k >> 3) & 3, tig = k & 3, vb = (k >> 2) & 1;
    const float vv[4] = {v.x, v.y, v.z, v.w};
#pragma unroll
    for (int e = 0; e < 4; e++) {
        int n = n4 + e;
        int coltile = n >> 7, nblk = (n >> 3) & 15, gidE = n & 7;
        int lane = (gidE * 4 + tig) ^ nblk;
        dst[((size_t)coltile * nc + c) * 4096 + ((nblk * 4 + ks) * 32 + lane) * 2 + vb] =
            __uint_as_float(f2tf32(vv[e]));
    }
}

__global__ __launch_bounds__(256) void k_packA_x(const float* __restrict__ x) {
    packA_body(x, g_pA, 1024);
}
__global__ __launch_bounds__(256) void k_packB_qkv(const float* __restrict__ w) {
    packB_body(w, g_pBq, 3072, 1024);
}
__global__ __launch_bounds__(256) void k_packB_out(const float* __restrict__ w) {
    packB_body(w, g_pBo, 1024, 1024);
}

// ---------------- packed tf32 GEMM (R9 2-stage version — known good) ----------------
#define G2_STAGE_WORDS 12288          // A 8192 + B 4096
#define G2_SMEM_BYTES (2 * G2_STAGE_WORDS * 4)   // 98304

__device__ __forceinline__ void gemm_packed_body(const float* __restrict__ gA,
                                                 const float* __restrict__ gB,
                                                 float* __restrict__ C,
                                                 int N, int K) {
    extern __shared__ unsigned dsm[];
    unsigned* buf0 = dsm;
    unsigned* buf1 = dsm + G2_STAGE_WORDS;

    const int tid = threadIdx.x;
    const int warp = tid >> 5, lane = tid & 31;
    const int gid = lane >> 2, tig = lane & 3;
    const int wr = warp & 3, wq = warp >> 2;
    const int nc = K >> 5;

    const char* Asrc = (const char*)(gA + (size_t)blockIdx.y * nc * 8192);
    const char* Bsrc = (const char*)(gB + (size_t)blockIdx.x * nc * 4096);
    const uint32_t sA0 = smem_u32(buf0);
    const uint32_t sA1 = smem_u32(buf1);

    float acc[4][8][4];
#pragma unroll
    for (int i = 0; i < 4; i++)
#pragma unroll
        for (int j = 0; j < 8; j++)
#pragma unroll
            for (int l = 0; l < 4; l++) acc[i][j][l] = 0.f;

    auto issue = [&](uint32_t sbuf, int c) {
        const char* a = Asrc + (size_t)c * 32768;
        const char* b = Bsrc + (size_t)c * 16384;
#pragma unroll
        for (int i = 0; i < 8; i++) {
            int off = (tid + i * 256) * 16;
            cp16(sbuf + off, a + off);
        }
#pragma unroll
        for (int i = 0; i < 4; i++) {
            int off = (tid + i * 256) * 16;
            cp16(sbuf + 32768 + off, b + off);
        }
    };

    issue(sA0, 0);
    asm volatile("cp.async.commit_group;" ::: "memory");

    for (int c = 0; c < nc; c++) {
        const int cur = c & 1;
        if (c + 1 < nc) {
            issue(cur ? sA0 : sA1, c + 1);
            asm volatile("cp.async.commit_group;" ::: "memory");
            asm volatile("cp.async.wait_group 1;" ::: "memory");
        } else {
            asm volatile("cp.async.wait_group 0;" ::: "memory");
        }
        __syncthreads();
        const unsigned* Ap = cur ? buf1 : buf0;
        const unsigned* Bp = Ap + 8192;
#pragma unroll
        for (int ks = 0; ks < 4; ks++) {
            uint4 a[4];
#pragma unroll
            for (int mt = 0; mt < 4; mt++)
                a[mt] = *(const uint4*)&Ap[(((wr * 4 + mt) * 4 + ks) * 32 + (lane ^ ks)) * 4];
#pragma unroll
            for (int nt = 0; nt < 8; nt++) {
                int nblk = wq * 8 + nt;
                uint2 bb = *(const uint2*)&Bp[((nblk * 4 + ks) * 32 + (lane ^ nblk)) * 2];
#pragma unroll
                for (int mt = 0; mt < 4; mt++)
                    mma_tf32(acc[mt][nt], (const unsigned*)&a[mt], bb.x, bb.y);
            }
        }
        __syncthreads();
    }

    float* Cb = C + (size_t)(blockIdx.y * 256) * N + blockIdx.x * 128;
#pragma unroll
    for (int mt = 0; mt < 4; mt++) {
#pragma unroll
        for (int nt = 0; nt < 8; nt++) {
            int r = wr * 64 + mt * 16 + gid;
            int cc = wq * 64 + nt * 8 + tig * 2;
            *(float2*)(Cb + (size_t)r * N + cc) =
                make_float2(acc[mt][nt][0], acc[mt][nt][1]);
            *(float2*)(Cb + (size_t)(r + 8) * N + cc) =
                make_float2(acc[mt][nt][2], acc[mt][nt][3]);
        }
    }
}

__global__ __launch_bounds__(256, 1) void k_gemm_qkv() {
    gemm_packed_body(g_pA, g_pBq, g_qkv, 3072, 1024);
}
__global__ __launch_bounds__(256, 1) void k_gemm_out(float* __restrict__ out) {
    gemm_packed_body(g_pA, g_pBo, out, 1024, 1024);
}

// ---------------- qa: register-tiled sim GEMM + fused softmax over m -> bf16 ----------------
__global__ __launch_bounds__(256) void k_qa(const float* __restrict__ agent) {
    extern __shared__ float fsm[];
    float* Qs = fsm;          // [64k][128n]
    float* Ams = fsm + 8192;  // [64k][128m]
    const int b = blockIdx.z, h = blockIdx.y, n0 = blockIdx.x * 128;
    const int t = threadIdx.x;

    {
        int m = t >> 1, kb = (t & 1) * 32;
        const float4* src = (const float4*)(agent + h * 8192 + m * 64 + kb);
#pragma unroll
        for (int i = 0; i < 8; i++) {
            float4 v = src[i];
            int k = kb + i * 4;
            Ams[(k + 0) * 128 + m] = v.x * SCALE_A;
            Ams[(k + 1) * 128 + m] = v.y * SCALE_A;
            Ams[(k + 2) * 128 + m] = v.z * SCALE_A;
            Ams[(k + 3) * 128 + m] = v.w * SCALE_A;
        }
    }
    {
        int n = t >> 1, kb = (t & 1) * 32;
        const float4* src = (const float4*)(g_qkv + ((size_t)(b * 4096 + n0 + n)) * 3072 + h * 64 + kb);
#pragma unroll
        for (int i = 0; i < 8; i++) {
            float4 v = src[i];
            int k = kb + i * 4;
            Qs[(k + 0) * 128 + n] = v.x;
            Qs[(k + 1) * 128 + n] = v.y;
            Qs[(k + 2) * 128 + n] = v.z;
            Qs[(k + 3) * 128 + n] = v.w;
        }
    }
    __syncthreads();

    const int tx = t & 15, ty = t >> 4;
    float acc[8][8];
#pragma unroll
    for (int i = 0; i < 8; i++)
#pragma unroll
        for (int j = 0; j < 8; j++) acc[i][j] = 0.f;

#pragma unroll 4
    for (int kk = 0; kk < 64; kk++) {
        float4 q0 = *(const float4*)&Qs[kk * 128 + ty * 4];
        float4 q1 = *(const float4*)&Qs[kk * 128 + 64 + ty * 4];
        float4 a0 = *(const float4*)&Ams[kk * 128 + tx * 4];
        float4 a1 = *(const float4*)&Ams[kk * 128 + 64 + tx * 4];
        const float qn[8] = {q0.x, q0.y, q0.z, q0.w, q1.x, q1.y, q1.z, q1.w};
        const float am[8] = {a0.x, a0.y, a0.z, a0.w, a1.x, a1.y, a1.z, a1.w};
#pragma unroll
        for (int i = 0; i < 8; i++)
#pragma unroll
            for (int j = 0; j < 8; j++) acc[i][j] += qn[i] * am[j];
    }

    const size_t base = ((size_t)(b * 16 + h)) * 524288;
#pragma unroll
    for (int i = 0; i < 8; i++) {
        float mx = acc[i][0];
#pragma unroll
        for (int j = 1; j < 8; j++) mx = fmaxf(mx, acc[i][j]);
#pragma unroll
        for (int off = 8; off > 0; off >>= 1)
            mx = fmaxf(mx, __shfl_xor_sync(0xffffffffu, mx, off));
        float e[8], sum = 0.f;
#pragma unroll
        for (int j = 0; j < 8; j++) { e[j] = __expf(acc[i][j] - mx); sum += e[j]; }
#pragma unroll
        for (int off = 8; off > 0; off >>= 1)
            sum += __shfl_xor_sync(0xffffffffu, sum, off);
        const float inv = 1.f / sum;
        const int n_i = n0 + ((i < 4) ? (ty * 4 + i) : (64 + ty * 4 + i - 4));
        __nv_bfloat16* row = g_qa + base + (size_t)n_i * 128;
        *(__nv_bfloat162*)(row + tx * 4) = __floats2bfloat162_rn(e[0] * inv, e[1] * inv);
        *(__nv_bfloat162*)(row + tx * 4 + 2) = __floats2bfloat162_rn(e[2] * inv, e[3] * inv);
        *(__nv_bfloat162*)(row + 64 + tx * 4) = __floats2bfloat162_rn(e[4] * inv, e[5] * inv);
        *(__nv_bfloat162*)(row + 64 + tx * 4 + 2) = __floats2bfloat162_rn(e[6] * inv, e[7] * inv);
    }
}

// ---------------- ak: register-tiled sim GEMM, raw sims [b,h,m,n] -> bf16 ----------------
__global__ __launch_bounds__(256) void k_ak_sim(const float* __restrict__ agent) {
    extern __shared__ float fsm[];
    float* Ks = fsm;          // [64k][128n]
    float* Ams = fsm + 8192;  // [64k][128m]
    const int b = blockIdx.z, h = blockIdx.y, n0 = blockIdx.x * 128;
    const int t = threadIdx.x;

    {
        int m = t >> 1, kb = (t & 1) * 32;
        const float4* src = (const float4*)(agent + h * 8192 + m * 64 + kb);
#pragma unroll
        for (int i = 0; i < 8; i++) {
            float4 v = src[i];
            int k = kb + i * 4;
            Ams[(k + 0) * 128 + m] = v.x * SCALE_A;
            Ams[(k + 1) * 128 + m] = v.y * SCALE_A;
            Ams[(k + 2) * 128 + m] = v.z * SCALE_A;
            Ams[(k + 3) * 128 + m] = v.w * SCALE_A;
        }
    }
    {
        int n = t >> 1, kb = (t & 1) * 32;
        const float4* src = (const float4*)(g_qkv + ((size_t)(b * 4096 + n0 + n)) * 3072 + 1024 + h * 64 + kb);
#pragma unroll
        for (int i = 0; i < 8; i++) {
            float4 v = src[i];
            int k = kb + i * 4;
            Ks[(k + 0) * 128 + n] = v.x;
            Ks[(k + 1) * 128 + n] = v.y;
            Ks[(k + 2) * 128 + n] = v.z;
            Ks[(k + 3) * 128 + n] = v.w;
        }
    }
    __syncthreads();

    const int tx = t & 15, ty = t >> 4;
    float acc[8][8];
#pragma unroll
    for (int i = 0; i < 8; i++)
#pragma unroll
        for (int j = 0; j < 8; j++) acc[i][j] = 0.f;

#pragma unroll 4
    for (int kk = 0; kk < 64; kk++) {
        float4 a0 = *(const float4*)&Ams[kk * 128 + ty * 4];
        float4 a1 = *(const float4*)&Ams[kk * 128 + 64 + ty * 4];
        float4 k0 = *(const float4*)&Ks[kk * 128 + tx * 4];
        float4 k1 = *(const float4*)&Ks[kk * 128 + 64 + tx * 4];
        const float am[8] = {a0.x, a0.y, a0.z, a0.w, a1.x, a1.y, a1.z, a1.w};
        const float kn[8] = {k0.x, k0.y, k0.z, k0.w, k1.x, k1.y, k1.z, k1.w};
#pragma unroll
        for (int i = 0; i < 8; i++)
#pragma unroll
            for (int j = 0; j < 8; j++) acc[i][j] += am[i] * kn[j];
    }

    const size_t base = ((size_t)(b * 16 + h)) * 524288;
#pragma unroll
    for (int i = 0; i < 8; i++) {
        const int m_i = (i < 4) ? (ty * 4 + i) : (64 + ty * 4 + i - 4);
        __nv_bfloat16* row = g_ak + base + (size_t)m_i * 4096 + n0;
        *(__nv_bfloat162*)(row + tx * 4) = __floats2bfloat162_rn(acc[i][0], acc[i][1]);
        *(__nv_bfloat162*)(row + tx * 4 + 2) = __floats2bfloat162_rn(acc[i][2], acc[i][3]);
        *(__nv_bfloat162*)(row + 64 + tx * 4) = __floats2bfloat162_rn(acc[i][4], acc[i][5]);
        *(__nv_bfloat162*)(row + 64 + tx * 4 + 2) = __floats2bfloat162_rn(acc[i][6], acc[i][7]);
    }
}

// ---------------- ak row stats: max + 1/sumexp per (b,h,m), masked (bf16 input) ------
__global__ __launch_bounds__(256) void k_ak_stats() {
    const int bhm = blockIdx.x;
    const int b = bhm >> 11;
    const __nv_bfloat16* row = g_ak + (size_t)bhm * 4096;
    const unsigned char* mrow = g_mask + b * 4096;
    const int t = threadIdx.x;

    float v[16];
    float mx = -3.402823e38f;
#pragma unroll
    for (int i = 0; i < 8; i++) {
        int p = t + i * 256;               // pair index, n = 2p, 2p+1
        float2 xv = bf2f(*(const __nv_bfloat162*)(row + p * 2));
        float x0 = mrow[p * 2] ? xv.x : -3.402823e38f;
        float x1 = mrow[p * 2 + 1] ? xv.y : -3.402823e38f;
        v[i * 2] = x0; v[i * 2 + 1] = x1;
        mx = fmaxf(mx, fmaxf(x0, x1));
    }
    __shared__ float red[256];
    red[t] = mx; __syncthreads();
    for (int s = 128; s > 0; s >>= 1) {
        if (t < s) red[t] = fmaxf(red[t], red[t + s]);
        __syncthreads();
    }
    mx = red[0]; __syncthreads();

    float sum = 0.f;
#pragma unroll
    for (int i = 0; i < 16; i++) sum += __expf(v[i] - mx);
    red[t] = sum; __syncthreads();
    for (int s = 128; s > 0; s >>= 1) {
        if (t < s) red[t] += red[t + s];
        __syncthreads();
    }
    if (t == 0) g_akstat[bhm] = make_float2(mx, 1.f / red[0]);
}

// ---------------- talking-heads mixes (bf16x2 per thread) ----------------
__global__ __launch_bounds__(256) void k_mix_qa(const float* __restrict__ W) {
    __shared__ float Ws[256];
    Ws[threadIdx.x] = W[threadIdx.x];
    __syncthreads();
    const size_t S2 = 262144;   // pairs per (b,head)
    const int b = blockIdx.y;
    const size_t s2 = (size_t)blockIdx.x * 256 + threadIdx.x;
    float2 v[16];
#pragma unroll
    for (int h = 0; h < 16; h++)
        v[h] = bf2f(*(const __nv_bfloat162*)(g_qa + ((size_t)(b * 16 + h) * S2 + s2) * 2));
#pragma unroll
    for (int g = 0; g < 16; g++) {
        float ox = 0.f, oy = 0.f;
#pragma unroll
        for (int h = 0; h < 16; h++) {
            float w = Ws[g * 16 + h];
            ox += w * v[h].x; oy += w * v[h].y;
        }
        *(__nv_bfloat162*)(g_qam + ((size_t)(b * 16 + g) * S2 + s2) * 2) =
            __floats2bfloat162_rn(ox, oy);
    }
}

__global__ __launch_bounds__(256) void k_mix_ak(const float* __restrict__ W) {
    __shared__ float Ws[256];
    Ws[threadIdx.x] = W[threadIdx.x];
    __syncthreads();
    const size_t S2 = 262144;   // pairs per (b,head); per m: 2048 pairs
    const int b = blockIdx.y;
    const size_t s2 = (size_t)blockIdx.x * 256 + threadIdx.x;
    const int m = (int)(s2 >> 11);
    const int n = (int)(s2 & 2047) * 2;
    const unsigned char mk0 = g_mask[b * 4096 + n];
    const unsigned char mk1 = g_mask[b * 4096 + n + 1];
    float2 v[16];
#pragma unroll
    for (int h = 0; h < 16; h++) {
        float2 raw = bf2f(*(const __nv_bfloat162*)(g_ak + ((size_t)(b * 16 + h) * S2 + s2) * 2));
        float2 st = g_akstat[(b * 16 + h) * 128 + m];
        v[h].x = mk0 ? __expf(raw.x - st.x) * st.y : 0.f;
        v[h].y = mk1 ? __expf(raw.y - st.x) * st.y : 0.f;
    }
#pragma unroll
    for (int g = 0; g < 16; g++) {
        float ox = 0.f, oy = 0.f;
#pragma unroll
        for (int h = 0; h < 16; h++) {
            float w = Ws[g * 16 + h];
            ox += w * v[h].x; oy += w * v[h].y;
        }
        *(__nv_bfloat162*)(g_akm + ((size_t)(b * 16 + g) * S2 + s2) * 2) =
            __floats2bfloat162_rn(ox, oy);
    }
}

// ---------------- agent_out partials: split n into 4 ranges (bf16 akm input) --------
__global__ __launch_bounds__(512) void k_agent_out() {
    __shared__ float akm_s[128 * 64];
    __shared__ float v_s[64 * 64];
    const int g = blockIdx.x, b = blockIdx.y, sp = blockIdx.z;
    const int t = threadIdx.x;
    const int d = t & 63, mg = t >> 6;
    const __nv_bfloat16* akm_b = g_akm + (size_t)(b * 16 + g) * 524288;
    const float* v_b = g_qkv + (size_t)b * 4096 * 3072 + 2048 + g * 64;

    float acc[16];
#pragma unroll
    for (int j = 0; j < 16; j++) acc[j] = 0.f;

    const int nlo = sp * 1024, nhi = nlo + 1024;
    for (int n0 = 0; n0 < 1024; n0 += 64) {
        const int nb = nlo + n0;
#pragma unroll
        for (int i = 0; i < 8; i++) {
            int pidx = t + i * 512;           // pair index: 4096 pairs = 128r x 32cp
            int r = pidx >> 5, cp = pidx & 31;
            float2 vv = bf2f(*(const __nv_bfloat162*)(akm_b + (size_t)r * 4096 + nb + cp * 2));
            *(float2*)&akm_s[r * 64 + cp * 2] = vv;
        }
#pragma unroll
        for (int i = 0; i < 8; i++) {
            int idx = t + i * 512;
            int r = idx >> 6, c = idx & 63;
            v_s[idx] = v_b[(size_t)(nb + r) * 3072 + c];
        }
        __syncthreads();
#pragma unroll 4
        for (int nn = 0; nn < 64; nn++) {
            float vv = v_s[nn * 64 + d];
#pragma unroll
            for (int j = 0; j < 16; j++)
                acc[j] += akm_s[(mg * 16 + j) * 64 + nn] * vv;
        }
        __syncthreads();
    }
    (void)nhi;
    float* out = g_aop + (size_t)sp * 524288 + (size_t)(b * 16 + g) * 8192;
#pragma unroll
    for (int j = 0; j < 16; j++) out[(mg * 16 + j) * 64 + d] = acc[j];
}

__global__ __launch_bounds__(256) void k_ao_reduce() {
    const int i = blockIdx.x * 256 + threadIdx.x;
    g_ao[i] = g_aop[i] + g_aop[524288 + i] + g_aop[1048576 + i] + g_aop[1572864 + i];
}

// ---------------- out_pre FUSED with packed-A epilogue (bf16 qam input) ----------------
__global__ __launch_bounds__(256) void k_out_pre() {
    extern __shared__ float fsm[];
    float* qs = fsm;          // [64m][128n]
    float* aos = fsm + 8192;  // [128m][64d]
    const int n0 = blockIdx.x * 128, g = blockIdx.y, b = blockIdx.z;
    const int t = threadIdx.x;
    const int tx = t & 15, ty = t >> 4;
    const __nv_bfloat16* qam_b = g_qam + (size_t)(b * 16 + g) * 524288;
    const float* ao_b = g_ao + (size_t)(b * 16 + g) * 8192;

#pragma unroll
    for (int i = 0; i < 8; i++) {
        int f = t + i * 256;
        int m = f >> 4, df = (f & 15) * 4;
        *(float4*)&aos[m * 64 + df] = *(const float4*)(ao_b + m * 64 + df);
    }

    float acc[8][4];
#pragma unroll
    for (int i = 0; i < 8; i++)
#pragma unroll
        for (int w = 0; w < 4; w++) acc[i][w] = 0.f;

    for (int mc = 0; mc < 128; mc += 64) {
        __syncthreads();
#pragma unroll
        for (int i = 0; i < 8; i++) {
            int f = t + i * 256;
            int n = f >> 4, mf = (f & 15) * 4;
            const __nv_bfloat16* src = qam_b + (size_t)(n0 + n) * 128 + mc + mf;
            float2 v01 = bf2f(*(const __nv_bfloat162*)(src));
            float2 v23 = bf2f(*(const __nv_bfloat162*)(src + 2));
            qs[(mf + 0) * 128 + n] = v01.x;
            qs[(mf + 1) * 128 + n] = v01.y;
            qs[(mf + 2) * 128 + n] = v23.x;
            qs[(mf + 3) * 128 + n] = v23.y;
        }
        __syncthreads();
#pragma unroll 4
        for (int mm = 0; mm < 64; mm++) {
            float4 r0 = *(const float4*)&qs[mm * 128 + ty * 4];
            float4 r1 = *(const float4*)&qs[mm * 128 + 64 + ty * 4];
            float4 rb = *(const float4*)&aos[(mc + mm) * 64 + tx * 4];
            const float rn[8] = {r0.x, r0.y, r0.z, r0.w, r1.x, r1.y, r1.z, r1.w};
            const float* bw = &rb.x;
#pragma unroll
            for (int i = 0; i < 8; i++)
#pragma unroll
                for (int w = 0; w < 4; w++) acc[i][w] += rn[i] * bw[w];
        }
    }

    // fused packed-A store: k = g*64 + tx*4 + w -> (c, ks, hi) fixed, tig = w
    const int kbase = g * 64 + tx * 4;
    const int kc = kbase >> 5;
    const int ks = (kbase >> 3) & 3;
    const int hi = (kbase >> 2) & 1;
#pragma unroll
    for (int i = 0; i < 8; i++) {
        const int n_i = n0 + ((i < 4) ? (ty * 4 + i) : (64 + ty * 4 + i - 4));
        const float msk = g_mask[b * 4096 + n_i] ? 1.f : 0.f;
        const int r = b * 4096 + n_i;
        const int rowtile = r >> 8, blk = (r >> 4) & 15, gidE = r & 7, hb = (r >> 3) & 1;
        const int j = hi * 2 + hb;
        float* base = g_pA + ((size_t)rowtile * 32 + kc) * 8192;
#pragma unroll
        for (int w = 0; w < 4; w++) {
            const int lane = (gidE * 4 + w) ^ ks;
            base[((blk * 4 + ks) * 32 + lane) * 4 + j] =
                __uint_as_float(f2tf32(acc[i][w] * msk));
        }
    }
}

// ---------------- launch ----------------
extern "C" void kernel_launch(void* const* d_in, const int* in_sizes, int n_in,
                              void* d_out, int out_size) {
    const float* x = (const float*)d_in[0];
    const void* mask_raw = d_in[1];
    const float* W_qkv = (const float*)d_in[2];
    const float* agent = (const float*)d_in[3];
    const float* W_qa = (const float*)d_in[4];
    const float* W_ak = (const float*)d_in[5];
    const float* W_out = (const float*)d_in[6];
    float* out = (float*)d_out;

    cudaFuncSetAttribute(k_gemm_qkv, cudaFuncAttributeMaxDynamicSharedMemorySize, G2_SMEM_BYTES);
    cudaFuncSetAttribute(k_gemm_out, cudaFuncAttributeMaxDynamicSharedMemorySize, G2_SMEM_BYTES);
    cudaFuncSetAttribute(k_qa, cudaFuncAttributeMaxDynamicSharedMemorySize, 65536);
    cudaFuncSetAttribute(k_ak_sim, cudaFuncAttributeMaxDynamicSharedMemorySize, 65536);
    cudaFuncSetAttribute(k_out_pre, cudaFuncAttributeMaxDynamicSharedMemorySize, 65536);

    // 0. mask canonicalization + operand packing
    k_mask_canon<<<1, 256>>>(mask_raw);
    k_packB_qkv<<<3072, 256>>>(W_qkv);
    k_packB_out<<<1024, 256>>>(W_out);
    k_packA_x<<<16384, 256>>>(x);
    // 1. qkv projection
    k_gemm_qkv<<<dim3(3072 / 128, 16384 / 256), 256, G2_SMEM_BYTES>>>();
    // 2. qa similarities + fused softmax (over m) -> bf16 [b,h,n,m]
    k_qa<<<dim3(32, 16, 4), 256, 65536>>>(agent);
    // 3. ak similarities (raw) -> bf16 [b,h,m,n]
    k_ak_sim<<<dim3(32, 16, 4), 256, 65536>>>(agent);
    // 4. ak row stats (masked max + 1/sumexp)
    k_ak_stats<<<8192, 256>>>();
    // 5. talking heads (bf16x2; ak mix applies softmax on the fly)
    k_mix_qa<<<dim3(1024, 4), 256>>>(W_qa);
    k_mix_ak<<<dim3(1024, 4), 256>>>(W_ak);
    // 6. agent_out = ak_mixed @ v (4-way n-split + reduce)
    k_agent_out<<<dim3(16, 4, 4), 512>>>();
    k_ao_reduce<<<2048, 256>>>();
    // 7. out_pre (+mask) written DIRECTLY in packed-A layout
    k_out_pre<<<dim3(32, 16, 4), 256, 65536>>>();
    // 8. final projection (no separate pack pass)
    k_gemm_out<<<dim3(1024 / 128, 16384 / 256), 256, G2_SMEM_BYTES>>>(out);
}

// round 15
// speedup vs baseline: 1.1784x; 1.0101x over previous
#include <cuda_runtime.h>
#include <cuda_bf16.h>
#include <math.h>
#include <stdint.h>

// Problem constants
// B=4, N=4096, DIM=1024, HEADS=16, DIM_HEAD=64, M=128, DIM_INNER=1024
#define SCALE_A 0.125f   // 64^-0.5

// ---------------- scratch (device globals; no runtime allocation) ----------------
// RULE (learned R2, re-learned R8): device globals may ONLY be referenced from
// device code. Host-side symbol addresses are invalid (GB300 ATS makes it silent).
__device__ float g_qkv[50331648];            // [4,4096,3072] fp32
__device__ __nv_bfloat16 g_qa[33554432];     // qa_attn  [b,h,n,m]  bf16
__device__ __nv_bfloat16 g_qam[33554432];    // qa mixed [b,g,n,m]  bf16
__device__ __nv_bfloat16 g_ak[33554432];     // ak raw sims [b,h,m,n] bf16
__device__ __nv_bfloat16 g_akm[33554432];    // ak mixed (softmaxed) [b,g,m,n] bf16
__device__ float2 g_akstat[8192];    // per (b,h,m): {rowmax, 1/sumexp}
__device__ float g_ao[524288];       // agent_out [b,g,m=128,d=64]
__device__ float g_aop[2097152];     // agent_out partials [4 splits][b,g,m,d]
__device__ unsigned char g_mask[16384]; // canonical uint8 mask [b,n]
__device__ float g_pA[16777216];     // packed A (16384x1024), reused by both GEMMs
__device__ float g_pBq[3145728];     // packed W_qkv (1024x3072)
__device__ float g_pBo[1048576];     // packed W_out (1024x1024)

// ---------------- helpers ----------------
__device__ __forceinline__ unsigned f2tf32(float x) {
    unsigned r;
    asm("cvt.rna.tf32.f32 %0, %1;" : "=r"(r) : "f"(x));
    return r;
}
__device__ __forceinline__ uint32_t smem_u32(const void* p) {
    uint32_t a;
    asm("{ .reg .u64 t; cvta.to.shared.u64 t, %1; cvt.u32.u64 %0, t; }" : "=r"(a) : "l"(p));
    return a;
}
__device__ __forceinline__ void cp16(uint32_t saddr, const void* g) {
    asm volatile("cp.async.cg.shared.global [%0], [%1], 16;" :: "r"(saddr), "l"(g));
}
__device__ __forceinline__ void mma_tf32(float* c, const unsigned* a,
                                         unsigned b0, unsigned b1) {
    asm volatile(
        "mma.sync.aligned.m16n8k8.row.col.f32.tf32.tf32.f32 "
        "{%0,%1,%2,%3}, {%4,%5,%6,%7}, {%8,%9}, {%0,%1,%2,%3};"
        : "+f"(c[0]), "+f"(c[1]), "+f"(c[2]), "+f"(c[3])
        : "r"(a[0]), "r"(a[1]), "r"(a[2]), "r"(a[3]), "r"(b0), "r"(b1));
}
__device__ __forceinline__ float2 bf2f(__nv_bfloat162 v) { return __bfloat1622float2(v); }

// ---------------- mask canonicalization ----------------
__global__ void k_mask_canon(const void* __restrict__ mraw) {
    __shared__ int notI32, notF32;
    if (threadIdx.x == 0) { notI32 = 0; notF32 = 0; }
    __syncthreads();
    const unsigned int* w = (const unsigned int*)mraw;
    int a = 0, b = 0;
    for (int i = threadIdx.x; i < 4096; i += 256) {
        unsigned int v = w[i];
        if (v > 1u) a = 1;
        if (v != 0u && v != 0x3F800000u) b = 1;
    }
    if (a) atomicOr(&notI32, 1);
    if (b) atomicOr(&notF32, 1);
    __syncthreads();
    const int mode = notI32 ? (notF32 ? 2 : 1) : 0;
    for (int i = threadIdx.x; i < 16384; i += 256) {
        unsigned char mv;
        if (mode == 0)      mv = (((const int*)mraw)[i] != 0);
        else if (mode == 1) mv = (((const float*)mraw)[i] != 0.0f);
        else                mv = (((const unsigned char*)mraw)[i] != 0);
        g_mask[i] = mv;
    }
}

// ---------------- operand pack bodies (R9 versions — known good) ----------------
__device__ __forceinline__ void packA_body(const float* __restrict__ src,
                                           float* __restrict__ dst, int K) {
    const size_t t = (size_t)blockIdx.x * 256 + threadIdx.x;
    const int kq = K >> 2;
    const int r = (int)(t / kq);
    const int k4 = (int)(t % kq) * 4;
    float4 v = *(const float4*)(src + (size_t)r * K + k4);
    const int nc = K >> 5;
    const int rowtile = r >> 8, blk = (r >> 4) & 15, gidE = r & 7, hb = (r >> 3) & 1;
    float* base = dst + (size_t)rowtile * nc * 8192;
    const float vv[4] = {v.x, v.y, v.z, v.w};
#pragma unroll
    for (int e = 0; e < 4; e++) {
        int k = k4 + e;
        int c = k >> 5, ks = (k >> 3) & 3, tig = k & 3, hi = (k >> 2) & 1;
        int lane = (gidE * 4 + tig) ^ ks;
        int j = hi * 2 + hb;
        base[(size_t)c * 8192 + ((blk * 4 + ks) * 32 + lane) * 4 + j] =
            __uint_as_float(f2tf32(vv[e]));
    }
}

__device__ __forceinline__ void packB_body(const float* __restrict__ src,
                                           float* __restrict__ dst, int N, int K) {
    const size_t t = (size_t)blockIdx.x * 256 + threadIdx.x;
    const int nq = N >> 2;
    const int k = (int)(t / nq);
    const int n4 = (int)(t % nq) * 4;
    float4 v = *(const float4*)(src + (size_t)k * N + n4);
    const int nc = K >> 5;
    const int c = k >> 5, ks = (k >> 3) & 3, tig = k & 3, vb = (k >> 2) & 1;
    const float vv[4] = {v.x, v.y, v.z, v.w};
#pragma unroll
    for (int e = 0; e < 4; e++) {
        int n = n4 + e;
        int coltile = n >> 7, nblk = (n >> 3) & 15, gidE = n & 7;
        int lane = (gidE * 4 + tig) ^ nblk;
        dst[((size_t)coltile * nc + c) * 4096 + ((nblk * 4 + ks) * 32 + lane) * 2 + vb] =
            __uint_as_float(f2tf32(vv[e]));
    }
}

__global__ __launch_bounds__(256) void k_packA_x(const float* __restrict__ x) {
    packA_body(x, g_pA, 1024);
}
__global__ __launch_bounds__(256) void k_packB_qkv(const float* __restrict__ w) {
    packB_body(w, g_pBq, 3072, 1024);
}
__global__ __launch_bounds__(256) void k_packB_out(const float* __restrict__ w) {
    packB_body(w, g_pBo, 1024, 1024);
}

// ---------------- packed tf32 GEMM (R9 2-stage version — known good) ----------------
#define G2_STAGE_WORDS 12288          // A 8192 + B 4096
#define G2_SMEM_BYTES (2 * G2_STAGE_WORDS * 4)   // 98304

__device__ __forceinline__ void gemm_packed_body(const float* __restrict__ gA,
                                                 const float* __restrict__ gB,
                                                 float* __restrict__ C,
                                                 int N, int K) {
    extern __shared__ unsigned dsm[];
    unsigned* buf0 = dsm;
    unsigned* buf1 = dsm + G2_STAGE_WORDS;

    const int tid = threadIdx.x;
    const int warp = tid >> 5, lane = tid & 31;
    const int gid = lane >> 2, tig = lane & 3;
    const int wr = warp & 3, wq = warp >> 2;
    const int nc = K >> 5;

    const char* Asrc = (const char*)(gA + (size_t)blockIdx.y * nc * 8192);
    const char* Bsrc = (const char*)(gB + (size_t)blockIdx.x * nc * 4096);
    const uint32_t sA0 = smem_u32(buf0);
    const uint32_t sA1 = smem_u32(buf1);

    float acc[4][8][4];
#pragma unroll
    for (int i = 0; i < 4; i++)
#pragma unroll
        for (int j = 0; j < 8; j++)
#pragma unroll
            for (int l = 0; l < 4; l++) acc[i][j][l] = 0.f;

    auto issue = [&](uint32_t sbuf, int c) {
        const char* a = Asrc + (size_t)c * 32768;
        const char* b = Bsrc + (size_t)c * 16384;
#pragma unroll
        for (int i = 0; i < 8; i++) {
            int off = (tid + i * 256) * 16;
            cp16(sbuf + off, a + off);
        }
#pragma unroll
        for (int i = 0; i < 4; i++) {
            int off = (tid + i * 256) * 16;
            cp16(sbuf + 32768 + off, b + off);
        }
    };

    issue(sA0, 0);
    asm volatile("cp.async.commit_group;" ::: "memory");

    for (int c = 0; c < nc; c++) {
        const int cur = c & 1;
        if (c + 1 < nc) {
            issue(cur ? sA0 : sA1, c + 1);
            asm volatile("cp.async.commit_group;" ::: "memory");
            asm volatile("cp.async.wait_group 1;" ::: "memory");
        } else {
            asm volatile("cp.async.wait_group 0;" ::: "memory");
        }
        __syncthreads();
        const unsigned* Ap = cur ? buf1 : buf0;
        const unsigned* Bp = Ap + 8192;
#pragma unroll
        for (int ks = 0; ks < 4; ks++) {
            uint4 a[4];
#pragma unroll
            for (int mt = 0; mt < 4; mt++)
                a[mt] = *(const uint4*)&Ap[(((wr * 4 + mt) * 4 + ks) * 32 + (lane ^ ks)) * 4];
#pragma unroll
            for (int nt = 0; nt < 8; nt++) {
                int nblk = wq * 8 + nt;
                uint2 bb = *(const uint2*)&Bp[((nblk * 4 + ks) * 32 + (lane ^ nblk)) * 2];
#pragma unroll
                for (int mt = 0; mt < 4; mt++)
                    mma_tf32(acc[mt][nt], (const unsigned*)&a[mt], bb.x, bb.y);
            }
        }
        __syncthreads();
    }

    float* Cb = C + (size_t)(blockIdx.y * 256) * N + blockIdx.x * 128;
#pragma unroll
    for (int mt = 0; mt < 4; mt++) {
#pragma unroll
        for (int nt = 0; nt < 8; nt++) {
            int r = wr * 64 + mt * 16 + gid;
            int cc = wq * 64 + nt * 8 + tig * 2;
            *(float2*)(Cb + (size_t)r * N + cc) =
                make_float2(acc[mt][nt][0], acc[mt][nt][1]);
            *(float2*)(Cb + (size_t)(r + 8) * N + cc) =
                make_float2(acc[mt][nt][2], acc[mt][nt][3]);
        }
    }
}

__global__ __launch_bounds__(256, 1) void k_gemm_qkv() {
    gemm_packed_body(g_pA, g_pBq, g_qkv, 3072, 1024);
}
__global__ __launch_bounds__(256, 1) void k_gemm_out(float* __restrict__ out) {
    gemm_packed_body(g_pA, g_pBo, out, 1024, 1024);
}

// ---------------- MERGED sims: phase 1 qa (+softmax over m), phase 2 ak ----------------
// Block (ntile, h, b), 256 threads. Agent tile loaded ONCE into Ams, reused.
__global__ __launch_bounds__(256) void k_sims(const float* __restrict__ agent) {
    extern __shared__ float fsm[];
    float* Xs = fsm;          // [64k][128n]  (Q in phase 1, K in phase 2)
    float* Ams = fsm + 8192;  // [64k][128m]
    const int b = blockIdx.z, h = blockIdx.y, n0 = blockIdx.x * 128;
    const int t = threadIdx.x;
    const int tx = t & 15, ty = t >> 4;
    const size_t base = ((size_t)(b * 16 + h)) * 524288;

    // agent tile (scaled), transposed to [k][m] — loaded once, used by both phases
    {
        int m = t >> 1, kb = (t & 1) * 32;
        const float4* src = (const float4*)(agent + h * 8192 + m * 64 + kb);
#pragma unroll
        for (int i = 0; i < 8; i++) {
            float4 v = src[i];
            int k = kb + i * 4;
            Ams[(k + 0) * 128 + m] = v.x * SCALE_A;
            Ams[(k + 1) * 128 + m] = v.y * SCALE_A;
            Ams[(k + 2) * 128 + m] = v.z * SCALE_A;
            Ams[(k + 3) * 128 + m] = v.w * SCALE_A;
        }
    }

    // ---------------- phase 1: qa ----------------
    {
        int n = t >> 1, kb = (t & 1) * 32;
        const float4* src = (const float4*)(g_qkv + ((size_t)(b * 4096 + n0 + n)) * 3072 + h * 64 + kb);
#pragma unroll
        for (int i = 0; i < 8; i++) {
            float4 v = src[i];
            int k = kb + i * 4;
            Xs[(k + 0) * 128 + n] = v.x;
            Xs[(k + 1) * 128 + n] = v.y;
            Xs[(k + 2) * 128 + n] = v.z;
            Xs[(k + 3) * 128 + n] = v.w;
        }
    }
    __syncthreads();

    {
        float acc[8][8];
#pragma unroll
        for (int i = 0; i < 8; i++)
#pragma unroll
            for (int j = 0; j < 8; j++) acc[i][j] = 0.f;

#pragma unroll 4
        for (int kk = 0; kk < 64; kk++) {
            float4 q0 = *(const float4*)&Xs[kk * 128 + ty * 4];
            float4 q1 = *(const float4*)&Xs[kk * 128 + 64 + ty * 4];
            float4 a0 = *(const float4*)&Ams[kk * 128 + tx * 4];
            float4 a1 = *(const float4*)&Ams[kk * 128 + 64 + tx * 4];
            const float qn[8] = {q0.x, q0.y, q0.z, q0.w, q1.x, q1.y, q1.z, q1.w};
            const float am[8] = {a0.x, a0.y, a0.z, a0.w, a1.x, a1.y, a1.z, a1.w};
#pragma unroll
            for (int i = 0; i < 8; i++)
#pragma unroll
                for (int j = 0; j < 8; j++) acc[i][j] += qn[i] * am[j];
        }

#pragma unroll
        for (int i = 0; i < 8; i++) {
            float mx = acc[i][0];
#pragma unroll
            for (int j = 1; j < 8; j++) mx = fmaxf(mx, acc[i][j]);
#pragma unroll
            for (int off = 8; off > 0; off >>= 1)
                mx = fmaxf(mx, __shfl_xor_sync(0xffffffffu, mx, off));
            float e[8], sum = 0.f;
#pragma unroll
            for (int j = 0; j < 8; j++) { e[j] = __expf(acc[i][j] - mx); sum += e[j]; }
#pragma unroll
            for (int off = 8; off > 0; off >>= 1)
                sum += __shfl_xor_sync(0xffffffffu, sum, off);
            const float inv = 1.f / sum;
            const int n_i = n0 + ((i < 4) ? (ty * 4 + i) : (64 + ty * 4 + i - 4));
            __nv_bfloat16* row = g_qa + base + (size_t)n_i * 128;
            *(__nv_bfloat162*)(row + tx * 4) = __floats2bfloat162_rn(e[0] * inv, e[1] * inv);
            *(__nv_bfloat162*)(row + tx * 4 + 2) = __floats2bfloat162_rn(e[2] * inv, e[3] * inv);
            *(__nv_bfloat162*)(row + 64 + tx * 4) = __floats2bfloat162_rn(e[4] * inv, e[5] * inv);
            *(__nv_bfloat162*)(row + 64 + tx * 4 + 2) = __floats2bfloat162_rn(e[6] * inv, e[7] * inv);
        }
    }

    // ---------------- phase 2: ak ----------------
    __syncthreads();   // protect Xs reuse
    {
        int n = t >> 1, kb = (t & 1) * 32;
        const float4* src = (const float4*)(g_qkv + ((size_t)(b * 4096 + n0 + n)) * 3072 + 1024 + h * 64 + kb);
#pragma unroll
        for (int i = 0; i < 8; i++) {
            float4 v = src[i];
            int k = kb + i * 4;
            Xs[(k + 0) * 128 + n] = v.x;
            Xs[(k + 1) * 128 + n] = v.y;
            Xs[(k + 2) * 128 + n] = v.z;
            Xs[(k + 3) * 128 + n] = v.w;
        }
    }
    __syncthreads();

    {
        float acc[8][8];    // [m][n] now: ty -> m, tx -> n
#pragma unroll
        for (int i = 0; i < 8; i++)
#pragma unroll
            for (int j = 0; j < 8; j++) acc[i][j] = 0.f;

#pragma unroll 4
        for (int kk = 0; kk < 64; kk++) {
            float4 a0 = *(const float4*)&Ams[kk * 128 + ty * 4];
            float4 a1 = *(const float4*)&Ams[kk * 128 + 64 + ty * 4];
            float4 k0 = *(const float4*)&Xs[kk * 128 + tx * 4];
            float4 k1 = *(const float4*)&Xs[kk * 128 + 64 + tx * 4];
            const float am[8] = {a0.x, a0.y, a0.z, a0.w, a1.x, a1.y, a1.z, a1.w};
            const float kn[8] = {k0.x, k0.y, k0.z, k0.w, k1.x, k1.y, k1.z, k1.w};
#pragma unroll
            for (int i = 0; i < 8; i++)
#pragma unroll
                for (int j = 0; j < 8; j++) acc[i][j] += am[i] * kn[j];
        }

#pragma unroll
        for (int i = 0; i < 8; i++) {
            const int m_i = (i < 4) ? (ty * 4 + i) : (64 + ty * 4 + i - 4);
            __nv_bfloat16* row = g_ak + base + (size_t)m_i * 4096 + n0;
            *(__nv_bfloat162*)(row + tx * 4) = __floats2bfloat162_rn(acc[i][0], acc[i][1]);
            *(__nv_bfloat162*)(row + tx * 4 + 2) = __floats2bfloat162_rn(acc[i][2], acc[i][3]);
            *(__nv_bfloat162*)(row + 64 + tx * 4) = __floats2bfloat162_rn(acc[i][4], acc[i][5]);
            *(__nv_bfloat162*)(row + 64 + tx * 4 + 2) = __floats2bfloat162_rn(acc[i][6], acc[i][7]);
        }
    }
}

// ---------------- ak row stats: max + 1/sumexp per (b,h,m), masked (bf16 input) ------
__global__ __launch_bounds__(256) void k_ak_stats() {
    const int bhm = blockIdx.x;
    const int b = bhm >> 11;
    const __nv_bfloat16* row = g_ak + (size_t)bhm * 4096;
    const unsigned char* mrow = g_mask + b * 4096;
    const int t = threadIdx.x;

    float v[16];
    float mx = -3.402823e38f;
#pragma unroll
    for (int i = 0; i < 8; i++) {
        int p = t + i * 256;               // pair index, n = 2p, 2p+1
        float2 xv = bf2f(*(const __nv_bfloat162*)(row + p * 2));
        float x0 = mrow[p * 2] ? xv.x : -3.402823e38f;
        float x1 = mrow[p * 2 + 1] ? xv.y : -3.402823e38f;
        v[i * 2] = x0; v[i * 2 + 1] = x1;
        mx = fmaxf(mx, fmaxf(x0, x1));
    }
    __shared__ float red[256];
    red[t] = mx; __syncthreads();
    for (int s = 128; s > 0; s >>= 1) {
        if (t < s) red[t] = fmaxf(red[t], red[t + s]);
        __syncthreads();
    }
    mx = red[0]; __syncthreads();

    float sum = 0.f;
#pragma unroll
    for (int i = 0; i < 16; i++) sum += __expf(v[i] - mx);
    red[t] = sum; __syncthreads();
    for (int s = 128; s > 0; s >>= 1) {
        if (t < s) red[t] += red[t + s];
        __syncthreads();
    }
    if (t == 0) g_akstat[bhm] = make_float2(mx, 1.f / red[0]);
}

// ---------------- talking-heads mixes (bf16x2 per thread) ----------------
__global__ __launch_bounds__(256) void k_mix_qa(const float* __restrict__ W) {
    __shared__ float Ws[256];
    Ws[threadIdx.x] = W[threadIdx.x];
    __syncthreads();
    const size_t S2 = 262144;   // pairs per (b,head)
    const int b = blockIdx.y;
    const size_t s2 = (size_t)blockIdx.x * 256 + threadIdx.x;
    float2 v[16];
#pragma unroll
    for (int h = 0; h < 16; h++)
        v[h] = bf2f(*(const __nv_bfloat162*)(g_qa + ((size_t)(b * 16 + h) * S2 + s2) * 2));
#pragma unroll
    for (int g = 0; g < 16; g++) {
        float ox = 0.f, oy = 0.f;
#pragma unroll
        for (int h = 0; h < 16; h++) {
            float w = Ws[g * 16 + h];
            ox += w * v[h].x; oy += w * v[h].y;
        }
        *(__nv_bfloat162*)(g_qam + ((size_t)(b * 16 + g) * S2 + s2) * 2) =
            __floats2bfloat162_rn(ox, oy);
    }
}

__global__ __launch_bounds__(256) void k_mix_ak(const float* __restrict__ W) {
    __shared__ float Ws[256];
    Ws[threadIdx.x] = W[threadIdx.x];
    __syncthreads();
    const size_t S2 = 262144;   // pairs per (b,head); per m: 2048 pairs
    const int b = blockIdx.y;
    const size_t s2 = (size_t)blockIdx.x * 256 + threadIdx.x;
    const int m = (int)(s2 >> 11);
    const int n = (int)(s2 & 2047) * 2;
    const unsigned char mk0 = g_mask[b * 4096 + n];
    const unsigned char mk1 = g_mask[b * 4096 + n + 1];
    float2 v[16];
#pragma unroll
    for (int h = 0; h < 16; h++) {
        float2 raw = bf2f(*(const __nv_bfloat162*)(g_ak + ((size_t)(b * 16 + h) * S2 + s2) * 2));
        float2 st = g_akstat[(b * 16 + h) * 128 + m];
        v[h].x = mk0 ? __expf(raw.x - st.x) * st.y : 0.f;
        v[h].y = mk1 ? __expf(raw.y - st.x) * st.y : 0.f;
    }
#pragma unroll
    for (int g = 0; g < 16; g++) {
        float ox = 0.f, oy = 0.f;
#pragma unroll
        for (int h = 0; h < 16; h++) {
            float w = Ws[g * 16 + h];
            ox += w * v[h].x; oy += w * v[h].y;
        }
        *(__nv_bfloat162*)(g_akm + ((size_t)(b * 16 + g) * S2 + s2) * 2) =
            __floats2bfloat162_rn(ox, oy);
    }
}

// ---------------- agent_out partials: split n into 4 ranges (bf16 akm input) --------
__global__ __launch_bounds__(512) void k_agent_out() {
    __shared__ float akm_s[128 * 64];
    __shared__ float v_s[64 * 64];
    const int g = blockIdx.x, b = blockIdx.y, sp = blockIdx.z;
    const int t = threadIdx.x;
    const int d = t & 63, mg = t >> 6;
    const __nv_bfloat16* akm_b = g_akm + (size_t)(b * 16 + g) * 524288;
    const float* v_b = g_qkv + (size_t)b * 4096 * 3072 + 2048 + g * 64;

    float acc[16];
#pragma unroll
    for (int j = 0; j < 16; j++) acc[j] = 0.f;

    const int nlo = sp * 1024;
    for (int n0 = 0; n0 < 1024; n0 += 64) {
        const int nb = nlo + n0;
#pragma unroll
        for (int i = 0; i < 8; i++) {
            int pidx = t + i * 512;           // pair index: 4096 pairs = 128r x 32cp
            int r = pidx >> 5, cp = pidx & 31;
            float2 vv = bf2f(*(const __nv_bfloat162*)(akm_b + (size_t)r * 4096 + nb + cp * 2));
            *(float2*)&akm_s[r * 64 + cp * 2] = vv;
        }
#pragma unroll
        for (int i = 0; i < 8; i++) {
            int idx = t + i * 512;
            int r = idx >> 6, c = idx & 63;
            v_s[idx] = v_b[(size_t)(nb + r) * 3072 + c];
        }
        __syncthreads();
#pragma unroll 4
        for (int nn = 0; nn < 64; nn++) {
            float vv = v_s[nn * 64 + d];
#pragma unroll
            for (int j = 0; j < 16; j++)
                acc[j] += akm_s[(mg * 16 + j) * 64 + nn] * vv;
        }
        __syncthreads();
    }
    float* out = g_aop + (size_t)sp * 524288 + (size_t)(b * 16 + g) * 8192;
#pragma unroll
    for (int j = 0; j < 16; j++) out[(mg * 16 + j) * 64 + d] = acc[j];
}

__global__ __launch_bounds__(256) void k_ao_reduce() {
    const int i = blockIdx.x * 256 + threadIdx.x;
    g_ao[i] = g_aop[i] + g_aop[524288 + i] + g_aop[1048576 + i] + g_aop[1572864 + i];
}

// ---------------- out_pre FUSED with packed-A epilogue (bf16 qam input) ----------------
__global__ __launch_bounds__(256) void k_out_pre() {
    extern __shared__ float fsm[];
    float* qs = fsm;          // [64m][128n]
    float* aos = fsm + 8192;  // [128m][64d]
    const int n0 = blockIdx.x * 128, g = blockIdx.y, b = blockIdx.z;
    const int t = threadIdx.x;
    const int tx = t & 15, ty = t >> 4;
    const __nv_bfloat16* qam_b = g_qam + (size_t)(b * 16 + g) * 524288;
    const float* ao_b = g_ao + (size_t)(b * 16 + g) * 8192;

#pragma unroll
    for (int i = 0; i < 8; i++) {
        int f = t + i * 256;
        int m = f >> 4, df = (f & 15) * 4;
        *(float4*)&aos[m * 64 + df] = *(const float4*)(ao_b + m * 64 + df);
    }

    float acc[8][4];
#pragma unroll
    for (int i = 0; i < 8; i++)
#pragma unroll
        for (int w = 0; w < 4; w++) acc[i][w] = 0.f;

    for (int mc = 0; mc < 128; mc += 64) {
        __syncthreads();
#pragma unroll
        for (int i = 0; i < 8; i++) {
            int f = t + i * 256;
            int n = f >> 4, mf = (f & 15) * 4;
            const __nv_bfloat16* src = qam_b + (size_t)(n0 + n) * 128 + mc + mf;
            float2 v01 = bf2f(*(const __nv_bfloat162*)(src));
            float2 v23 = bf2f(*(const __nv_bfloat162*)(src + 2));
            qs[(mf + 0) * 128 + n] = v01.x;
            qs[(mf + 1) * 128 + n] = v01.y;
            qs[(mf + 2) * 128 + n] = v23.x;
            qs[(mf + 3) * 128 + n] = v23.y;
        }
        __syncthreads();
#pragma unroll 4
        for (int mm = 0; mm < 64; mm++) {
            float4 r0 = *(const float4*)&qs[mm * 128 + ty * 4];
            float4 r1 = *(const float4*)&qs[mm * 128 + 64 + ty * 4];
            float4 rb = *(const float4*)&aos[(mc + mm) * 64 + tx * 4];
            const float rn[8] = {r0.x, r0.y, r0.z, r0.w, r1.x, r1.y, r1.z, r1.w};
            const float* bw = &rb.x;
#pragma unroll
            for (int i = 0; i < 8; i++)
#pragma unroll
                for (int w = 0; w < 4; w++) acc[i][w] += rn[i] * bw[w];
        }
    }

    // fused packed-A store: k = g*64 + tx*4 + w -> (c, ks, hi) fixed, tig = w
    const int kbase = g * 64 + tx * 4;
    const int kc = kbase >> 5;
    const int ks = (kbase >> 3) & 3;
    const int hi = (kbase >> 2) & 1;
#pragma unroll
    for (int i = 0; i < 8; i++) {
        const int n_i = n0 + ((i < 4) ? (ty * 4 + i) : (64 + ty * 4 + i - 4));
        const float msk = g_mask[b * 4096 + n_i] ? 1.f : 0.f;
        const int r = b * 4096 + n_i;
        const int rowtile = r >> 8, blk = (r >> 4) & 15, gidE = r & 7, hb = (r >> 3) & 1;
        const int j = hi * 2 + hb;
        float* base = g_pA + ((size_t)rowtile * 32 + kc) * 8192;
#pragma unroll
        for (int w = 0; w < 4; w++) {
            const int lane = (gidE * 4 + w) ^ ks;
            base[((blk * 4 + ks) * 32 + lane) * 4 + j] =
                __uint_as_float(f2tf32(acc[i][w] * msk));
        }
    }
}

// ---------------- launch ----------------
extern "C" void kernel_launch(void* const* d_in, const int* in_sizes, int n_in,
                              void* d_out, int out_size) {
    const float* x = (const float*)d_in[0];
    const void* mask_raw = d_in[1];
    const float* W_qkv = (const float*)d_in[2];
    const float* agent = (const float*)d_in[3];
    const float* W_qa = (const float*)d_in[4];
    const float* W_ak = (const float*)d_in[5];
    const float* W_out = (const float*)d_in[6];
    float* out = (float*)d_out;

    cudaFuncSetAttribute(k_gemm_qkv, cudaFuncAttributeMaxDynamicSharedMemorySize, G2_SMEM_BYTES);
    cudaFuncSetAttribute(k_gemm_out, cudaFuncAttributeMaxDynamicSharedMemorySize, G2_SMEM_BYTES);
    cudaFuncSetAttribute(k_sims, cudaFuncAttributeMaxDynamicSharedMemorySize, 65536);
    cudaFuncSetAttribute(k_out_pre, cudaFuncAttributeMaxDynamicSharedMemorySize, 65536);

    // launch order chosen so k_gemm_qkv is the 4th launch (profiled slot)
    // 0/1/2. mask + pack (packB_out deferred past the QKV GEMM; no dependency)
    k_mask_canon<<<1, 256>>>(mask_raw);
    k_packB_qkv<<<3072, 256>>>(W_qkv);
    k_packA_x<<<16384, 256>>>(x);
    // 3. qkv projection  <-- 4th launch: profiled
    k_gemm_qkv<<<dim3(3072 / 128, 16384 / 256), 256, G2_SMEM_BYTES>>>();
    // 4. pack W_out (only needed before gemm_out)
    k_packB_out<<<1024, 256>>>(W_out);
    // 5. merged qa (+softmax) and ak sims
    k_sims<<<dim3(32, 16, 4), 256, 65536>>>(agent);
    // 6. ak row stats (masked max + 1/sumexp)
    k_ak_stats<<<8192, 256>>>();
    // 7. talking heads (bf16x2; ak mix applies softmax on the fly)
    k_mix_qa<<<dim3(1024, 4), 256>>>(W_qa);
    k_mix_ak<<<dim3(1024, 4), 256>>>(W_ak);
    // 8. agent_out = ak_mixed @ v (4-way n-split + reduce)
    k_agent_out<<<dim3(16, 4, 4), 512>>>();
    k_ao_reduce<<<2048, 256>>>();
    // 9. out_pre (+mask) written DIRECTLY in packed-A layout
    k_out_pre<<<dim3(32, 16, 4), 256, 65536>>>();
    // 10. final projection
    k_gemm_out<<<dim3(1024 / 128, 16384 / 256), 256, G2_SMEM_BYTES>>>(out);
}

// round 17
// speedup vs baseline: 1.2634x; 1.0721x over previous
#include <cuda_runtime.h>
#include <cuda_bf16.h>
#include <math.h>
#include <stdint.h>

// Problem constants
// B=4, N=4096, DIM=1024, HEADS=16, DIM_HEAD=64, M=128, DIM_INNER=1024
#define SCALE_A 0.125f   // 64^-0.5

// ---------------- scratch (device globals; no runtime allocation) ----------------
// RULE (learned R2, re-learned R8): device globals may ONLY be referenced from
// device code. Host-side symbol addresses are invalid (GB300 ATS makes it silent).
__device__ float g_qkv[50331648];            // [4,4096,3072] fp32
__device__ __nv_bfloat16 g_qa[33554432];     // qa_attn  [b,h,n,m]  bf16
__device__ __nv_bfloat16 g_qam[33554432];    // qa mixed [b,g,n,m]  bf16
__device__ __nv_bfloat16 g_ak[33554432];     // ak raw sims [b,h,m,n] bf16
__device__ __nv_bfloat16 g_akm[33554432];    // ak mixed (softmaxed) [b,g,m,n] bf16
__device__ float2 g_akstat[8192];    // per (b,h,m): {rowmax, 1/sumexp}
__device__ float g_ao[524288];       // agent_out [b,g,m=128,d=64]
__device__ float g_aop[2097152];     // agent_out partials [4 splits][b,g,m,d]
__device__ unsigned char g_mask[16384]; // canonical uint8 mask [b,n]
__device__ float g_pA[16777216];     // packed A (16384x1024), reused by both GEMMs
__device__ float g_pBq[3145728];     // packed W_qkv (1024x3072)
__device__ float g_pBo[1048576];     // packed W_out (1024x1024)

// ---------------- helpers ----------------
__device__ __forceinline__ unsigned f2tf32(float x) {
    unsigned r;
    asm("cvt.rna.tf32.f32 %0, %1;" : "=r"(r) : "f"(x));
    return r;
}
__device__ __forceinline__ uint32_t smem_u32(const void* p) {
    uint32_t a;
    asm("{ .reg .u64 t; cvta.to.shared.u64 t, %1; cvt.u32.u64 %0, t; }" : "=r"(a) : "l"(p));
    return a;
}
__device__ __forceinline__ void cp16(uint32_t saddr, const void* g) {
    asm volatile("cp.async.cg.shared.global [%0], [%1], 16;" :: "r"(saddr), "l"(g));
}
__device__ __forceinline__ void mma_tf32(float* c, const unsigned* a,
                                         unsigned b0, unsigned b1) {
    asm volatile(
        "mma.sync.aligned.m16n8k8.row.col.f32.tf32.tf32.f32 "
        "{%0,%1,%2,%3}, {%4,%5,%6,%7}, {%8,%9}, {%0,%1,%2,%3};"
        : "+f"(c[0]), "+f"(c[1]), "+f"(c[2]), "+f"(c[3])
        : "r"(a[0]), "r"(a[1]), "r"(a[2]), "r"(a[3]), "r"(b0), "r"(b1));
}
__device__ __forceinline__ float2 bf2f(__nv_bfloat162 v) { return __bfloat1622float2(v); }

// ---------------- mask canonicalization ----------------
__global__ void k_mask_canon(const void* __restrict__ mraw) {
    __shared__ int notI32, notF32;
    if (threadIdx.x == 0) { notI32 = 0; notF32 = 0; }
    __syncthreads();
    const unsigned int* w = (const unsigned int*)mraw;
    int a = 0, b = 0;
    for (int i = threadIdx.x; i < 4096; i += 256) {
        unsigned int v = w[i];
        if (v > 1u) a = 1;
        if (v != 0u && v != 0x3F800000u) b = 1;
    }
    if (a) atomicOr(&notI32, 1);
    if (b) atomicOr(&notF32, 1);
    __syncthreads();
    const int mode = notI32 ? (notF32 ? 2 : 1) : 0;
    for (int i = threadIdx.x; i < 16384; i += 256) {
        unsigned char mv;
        if (mode == 0)      mv = (((const int*)mraw)[i] != 0);
        else if (mode == 1) mv = (((const float*)mraw)[i] != 0.0f);
        else                mv = (((const unsigned char*)mraw)[i] != 0);
        g_mask[i] = mv;
    }
}

// ---------------- operand pack bodies (R9 versions — known good) ----------------
__device__ __forceinline__ void packA_body(const float* __restrict__ src,
                                           float* __restrict__ dst, int K) {
    const size_t t = (size_t)blockIdx.x * 256 + threadIdx.x;
    const int kq = K >> 2;
    const int r = (int)(t / kq);
    const int k4 = (int)(t % kq) * 4;
    float4 v = *(const float4*)(src + (size_t)r * K + k4);
    const int nc = K >> 5;
    const int rowtile = r >> 8, blk = (r >> 4) & 15, gidE = r & 7, hb = (r >> 3) & 1;
    float* base = dst + (size_t)rowtile * nc * 8192;
    const float vv[4] = {v.x, v.y, v.z, v.w};
#pragma unroll
    for (int e = 0; e < 4; e++) {
        int k = k4 + e;
        int c = k >> 5, ks = (k >> 3) & 3, tig = k & 3, hi = (k >> 2) & 1;
        int lane = (gidE * 4 + tig) ^ ks;
        int j = hi * 2 + hb;
        base[(size_t)c * 8192 + ((blk * 4 + ks) * 32 + lane) * 4 + j] =
            __uint_as_float(f2tf32(vv[e]));
    }
}

__device__ __forceinline__ void packB_body(const float* __restrict__ src,
                                           float* __restrict__ dst, int N, int K) {
    const size_t t = (size_t)blockIdx.x * 256 + threadIdx.x;
    const int nq = N >> 2;
    const int k = (int)(t / nq);
    const int n4 = (int)(t % nq) * 4;
    float4 v = *(const float4*)(src + (size_t)k * N + n4);
    const int nc = K >> 5;
    const int c = k >> 5, ks = (k >> 3) & 3, tig = k & 3, vb = (k >> 2) & 1;
    const float vv[4] = {v.x, v.y, v.z, v.w};
#pragma unroll
    for (int e = 0; e < 4; e++) {
        int n = n4 + e;
        int coltile = n >> 7, nblk = (n >> 3) & 15, gidE = n & 7;
        int lane = (gidE * 4 + tig) ^ nblk;
        dst[((size_t)coltile * nc + c) * 4096 + ((nblk * 4 + ks) * 32 + lane) * 2 + vb] =
            __uint_as_float(f2tf32(vv[e]));
    }
}

__global__ __launch_bounds__(256) void k_packA_x(const float* __restrict__ x) {
    packA_body(x, g_pA, 1024);
}
__global__ __launch_bounds__(256) void k_packB_qkv(const float* __restrict__ w) {
    packB_body(w, g_pBq, 3072, 1024);
}
__global__ __launch_bounds__(256) void k_packB_out(const float* __restrict__ w) {
    packB_body(w, g_pBo, 1024, 1024);
}

// ---------------- packed tf32 GEMM: CTA 128x128, 4 warps, 2 CTAs/SM ----------------
// Warp tile 64x64 (2m x 2n warps), BK=32, cp.async double-buffer, 32KB/stage.
// A CTA covers HALF of a packed-A 256-row rowtile: blks 0-7 (half 0) are words
// [0,4096) of the 8192-word block, blks 8-15 (half 1) are words [4096,8192).
#define G3_STAGE_WORDS 8192           // A 4096 + B 4096
#define G3_SMEM_BYTES (2 * G3_STAGE_WORDS * 4)   // 65536

__device__ __forceinline__ void gemm_packed_body(const float* __restrict__ gA,
                                                 const float* __restrict__ gB,
                                                 float* __restrict__ C,
                                                 int N, int K) {
    extern __shared__ unsigned dsm[];
    unsigned* buf0 = dsm;
    unsigned* buf1 = dsm + G3_STAGE_WORDS;

    const int tid = threadIdx.x;
    const int warp = tid >> 5, lane = tid & 31;
    const int gid = lane >> 2, tig = lane & 3;
    const int wr = warp & 1, wq = warp >> 1;
    const int nc = K >> 5;
    const int rt = blockIdx.y >> 1, half = blockIdx.y & 1;

    const char* Asrc = (const char*)(gA + (size_t)rt * nc * 8192 + half * 4096);
    const char* Bsrc = (const char*)(gB + (size_t)blockIdx.x * nc * 4096);
    const uint32_t sA0 = smem_u32(buf0);
    const uint32_t sA1 = smem_u32(buf1);

    float acc[4][8][4];
#pragma unroll
    for (int i = 0; i < 4; i++)
#pragma unroll
        for (int j = 0; j < 8; j++)
#pragma unroll
            for (int l = 0; l < 4; l++) acc[i][j][l] = 0.f;

    auto issue = [&](uint32_t sbuf, int c) {
        const char* a = Asrc + (size_t)c * 32768;   // chunk stride = full 8192-word block
        const char* b = Bsrc + (size_t)c * 16384;
#pragma unroll
        for (int i = 0; i < 8; i++) {
            int off = (tid + i * 128) * 16;
            cp16(sbuf + off, a + off);
        }
#pragma unroll
        for (int i = 0; i < 8; i++) {
            int off = (tid + i * 128) * 16;
            cp16(sbuf + 16384 + off, b + off);
        }
    };

    issue(sA0, 0);
    asm volatile("cp.async.commit_group;" ::: "memory");

    for (int c = 0; c < nc; c++) {
        const int cur = c & 1;
        if (c + 1 < nc) {
            issue(cur ? sA0 : sA1, c + 1);
            asm volatile("cp.async.commit_group;" ::: "memory");
            asm volatile("cp.async.wait_group 1;" ::: "memory");
        } else {
            asm volatile("cp.async.wait_group 0;" ::: "memory");
        }
        __syncthreads();
        const unsigned* Ap = cur ? buf1 : buf0;
        const unsigned* Bp = Ap + 4096;
#pragma unroll
        for (int ks = 0; ks < 4; ks++) {
            uint4 a[4];
#pragma unroll
            for (int mt = 0; mt < 4; mt++)
                a[mt] = *(const uint4*)&Ap[(((wr * 4 + mt) * 4 + ks) * 32 + (lane ^ ks)) * 4];
#pragma unroll
            for (int nt = 0; nt < 8; nt++) {
                int nblk = wq * 8 + nt;
                uint2 bb = *(const uint2*)&Bp[((nblk * 4 + ks) * 32 + (lane ^ nblk)) * 2];
#pragma unroll
                for (int mt = 0; mt < 4; mt++)
                    mma_tf32(acc[mt][nt], (const unsigned*)&a[mt], bb.x, bb.y);
            }
        }
        __syncthreads();
    }

    float* Cb = C + (size_t)(blockIdx.y * 128) * N + blockIdx.x * 128;
#pragma unroll
    for (int mt = 0; mt < 4; mt++) {
#pragma unroll
        for (int nt = 0; nt < 8; nt++) {
            int r = wr * 64 + mt * 16 + gid;
            int cc = wq * 64 + nt * 8 + tig * 2;
            *(float2*)(Cb + (size_t)r * N + cc) =
                make_float2(acc[mt][nt][0], acc[mt][nt][1]);
            *(float2*)(Cb + (size_t)(r + 8) * N + cc) =
                make_float2(acc[mt][nt][2], acc[mt][nt][3]);
        }
    }
}

__global__ __launch_bounds__(128, 2) void k_gemm_qkv() {
    gemm_packed_body(g_pA, g_pBq, g_qkv, 3072, 1024);
}
__global__ __launch_bounds__(128, 2) void k_gemm_out(float* __restrict__ out) {
    gemm_packed_body(g_pA, g_pBo, out, 1024, 1024);
}

// ---------------- MERGED sims: phase 1 qa (+softmax over m), phase 2 ak ----------------
__global__ __launch_bounds__(256) void k_sims(const float* __restrict__ agent) {
    extern __shared__ float fsm[];
    float* Xs = fsm;          // [64k][128n]  (Q in phase 1, K in phase 2)
    float* Ams = fsm + 8192;  // [64k][128m]
    const int b = blockIdx.z, h = blockIdx.y, n0 = blockIdx.x * 128;
    const int t = threadIdx.x;
    const int tx = t & 15, ty = t >> 4;
    const size_t base = ((size_t)(b * 16 + h)) * 524288;

    {
        int m = t >> 1, kb = (t & 1) * 32;
        const float4* src = (const float4*)(agent + h * 8192 + m * 64 + kb);
#pragma unroll
        for (int i = 0; i < 8; i++) {
            float4 v = src[i];
            int k = kb + i * 4;
            Ams[(k + 0) * 128 + m] = v.x * SCALE_A;
            Ams[(k + 1) * 128 + m] = v.y * SCALE_A;
            Ams[(k + 2) * 128 + m] = v.z * SCALE_A;
            Ams[(k + 3) * 128 + m] = v.w * SCALE_A;
        }
    }

    // ---------------- phase 1: qa ----------------
    {
        int n = t >> 1, kb = (t & 1) * 32;
        const float4* src = (const float4*)(g_qkv + ((size_t)(b * 4096 + n0 + n)) * 3072 + h * 64 + kb);
#pragma unroll
        for (int i = 0; i < 8; i++) {
            float4 v = src[i];
            int k = kb + i * 4;
            Xs[(k + 0) * 128 + n] = v.x;
            Xs[(k + 1) * 128 + n] = v.y;
            Xs[(k + 2) * 128 + n] = v.z;
            Xs[(k + 3) * 128 + n] = v.w;
        }
    }
    __syncthreads();

    {
        float acc[8][8];
#pragma unroll
        for (int i = 0; i < 8; i++)
#pragma unroll
            for (int j = 0; j < 8; j++) acc[i][j] = 0.f;

#pragma unroll 4
        for (int kk = 0; kk < 64; kk++) {
            float4 q0 = *(const float4*)&Xs[kk * 128 + ty * 4];
            float4 q1 = *(const float4*)&Xs[kk * 128 + 64 + ty * 4];
            float4 a0 = *(const float4*)&Ams[kk * 128 + tx * 4];
            float4 a1 = *(const float4*)&Ams[kk * 128 + 64 + tx * 4];
            const float qn[8] = {q0.x, q0.y, q0.z, q0.w, q1.x, q1.y, q1.z, q1.w};
            const float am[8] = {a0.x, a0.y, a0.z, a0.w, a1.x, a1.y, a1.z, a1.w};
#pragma unroll
            for (int i = 0; i < 8; i++)
#pragma unroll
                for (int j = 0; j < 8; j++) acc[i][j] += qn[i] * am[j];
        }

#pragma unroll
        for (int i = 0; i < 8; i++) {
            float mx = acc[i][0];
#pragma unroll
            for (int j = 1; j < 8; j++) mx = fmaxf(mx, acc[i][j]);
#pragma unroll
            for (int off = 8; off > 0; off >>= 1)
                mx = fmaxf(mx, __shfl_xor_sync(0xffffffffu, mx, off));
            float e[8], sum = 0.f;
#pragma unroll
            for (int j = 0; j < 8; j++) { e[j] = __expf(acc[i][j] - mx); sum += e[j]; }
#pragma unroll
            for (int off = 8; off > 0; off >>= 1)
                sum += __shfl_xor_sync(0xffffffffu, sum, off);
            const float inv = 1.f / sum;
            const int n_i = n0 + ((i < 4) ? (ty * 4 + i) : (64 + ty * 4 + i - 4));
            __nv_bfloat16* row = g_qa + base + (size_t)n_i * 128;
            *(__nv_bfloat162*)(row + tx * 4) = __floats2bfloat162_rn(e[0] * inv, e[1] * inv);
            *(__nv_bfloat162*)(row + tx * 4 + 2) = __floats2bfloat162_rn(e[2] * inv, e[3] * inv);
            *(__nv_bfloat162*)(row + 64 + tx * 4) = __floats2bfloat162_rn(e[4] * inv, e[5] * inv);
            *(__nv_bfloat162*)(row + 64 + tx * 4 + 2) = __floats2bfloat162_rn(e[6] * inv, e[7] * inv);
        }
    }

    // ---------------- phase 2: ak ----------------
    __syncthreads();   // protect Xs reuse
    {
        int n = t >> 1, kb = (t & 1) * 32;
        const float4* src = (const float4*)(g_qkv + ((size_t)(b * 4096 + n0 + n)) * 3072 + 1024 + h * 64 + kb);
#pragma unroll
        for (int i = 0; i < 8; i++) {
            float4 v = src[i];
            int k = kb + i * 4;
            Xs[(k + 0) * 128 + n] = v.x;
            Xs[(k + 1) * 128 + n] = v.y;
            Xs[(k + 2) * 128 + n] = v.z;
            Xs[(k + 3) * 128 + n] = v.w;
        }
    }
    __syncthreads();

    {
        float acc[8][8];    // [m][n] now: ty -> m, tx -> n
#pragma unroll
        for (int i = 0; i < 8; i++)
#pragma unroll
            for (int j = 0; j < 8; j++) acc[i][j] = 0.f;

#pragma unroll 4
        for (int kk = 0; kk < 64; kk++) {
            float4 a0 = *(const float4*)&Ams[kk * 128 + ty * 4];
            float4 a1 = *(const float4*)&Ams[kk * 128 + 64 + ty * 4];
            float4 k0 = *(const float4*)&Xs[kk * 128 + tx * 4];
            float4 k1 = *(const float4*)&Xs[kk * 128 + 64 + tx * 4];
            const float am[8] = {a0.x, a0.y, a0.z, a0.w, a1.x, a1.y, a1.z, a1.w};
            const float kn[8] = {k0.x, k0.y, k0.z, k0.w, k1.x, k1.y, k1.z, k1.w};
#pragma unroll
            for (int i = 0; i < 8; i++)
#pragma unroll
                for (int j = 0; j < 8; j++) acc[i][j] += am[i] * kn[j];
        }

#pragma unroll
        for (int i = 0; i < 8; i++) {
            const int m_i = (i < 4) ? (ty * 4 + i) : (64 + ty * 4 + i - 4);
            __nv_bfloat16* row = g_ak + base + (size_t)m_i * 4096 + n0;
            *(__nv_bfloat162*)(row + tx * 4) = __floats2bfloat162_rn(acc[i][0], acc[i][1]);
            *(__nv_bfloat162*)(row + tx * 4 + 2) = __floats2bfloat162_rn(acc[i][2], acc[i][3]);
            *(__nv_bfloat162*)(row + 64 + tx * 4) = __floats2bfloat162_rn(acc[i][4], acc[i][5]);
            *(__nv_bfloat162*)(row + 64 + tx * 4 + 2) = __floats2bfloat162_rn(acc[i][6], acc[i][7]);
        }
    }
}

// ---------------- ak row stats: max + 1/sumexp per (b,h,m), masked (bf16 input) ------
__global__ __launch_bounds__(256) void k_ak_stats() {
    const int bhm = blockIdx.x;
    const int b = bhm >> 11;
    const __nv_bfloat16* row = g_ak + (size_t)bhm * 4096;
    const unsigned char* mrow = g_mask + b * 4096;
    const int t = threadIdx.x;

    float v[16];
    float mx = -3.402823e38f;
#pragma unroll
    for (int i = 0; i < 8; i++) {
        int p = t + i * 256;               // pair index, n = 2p, 2p+1
        float2 xv = bf2f(*(const __nv_bfloat162*)(row + p * 2));
        float x0 = mrow[p * 2] ? xv.x : -3.402823e38f;
        float x1 = mrow[p * 2 + 1] ? xv.y : -3.402823e38f;
        v[i * 2] = x0; v[i * 2 + 1] = x1;
        mx = fmaxf(mx, fmaxf(x0, x1));
    }
    __shared__ float red[256];
    red[t] = mx; __syncthreads();
    for (int s = 128; s > 0; s >>= 1) {
        if (t < s) red[t] = fmaxf(red[t], red[t + s]);
        __syncthreads();
    }
    mx = red[0]; __syncthreads();

    float sum = 0.f;
#pragma unroll
    for (int i = 0; i < 16; i++) sum += __expf(v[i] - mx);
    red[t] = sum; __syncthreads();
    for (int s = 128; s > 0; s >>= 1) {
        if (t < s) red[t] += red[t + s];
        __syncthreads();
    }
    if (t == 0) g_akstat[bhm] = make_float2(mx, 1.f / red[0]);
}

// ---------------- talking-heads mixes (bf16x2 per thread) ----------------
__global__ __launch_bounds__(256) void k_mix_qa(const float* __restrict__ W) {
    __shared__ float Ws[256];
    Ws[threadIdx.x] = W[threadIdx.x];
    __syncthreads();
    const size_t S2 = 262144;   // pairs per (b,head)
    const int b = blockIdx.y;
    const size_t s2 = (size_t)blockIdx.x * 256 + threadIdx.x;
    float2 v[16];
#pragma unroll
    for (int h = 0; h < 16; h++)
        v[h] = bf2f(*(const __nv_bfloat162*)(g_qa + ((size_t)(b * 16 + h) * S2 + s2) * 2));
#pragma unroll
    for (int g = 0; g < 16; g++) {
        float ox = 0.f, oy = 0.f;
#pragma unroll
        for (int h = 0; h < 16; h++) {
            float w = Ws[g * 16 + h];
            ox += w * v[h].x; oy += w * v[h].y;
        }
        *(__nv_bfloat162*)(g_qam + ((size_t)(b * 16 + g) * S2 + s2) * 2) =
            __floats2bfloat162_rn(ox, oy);
    }
}

__global__ __launch_bounds__(256) void k_mix_ak(const float* __restrict__ W) {
    __shared__ float Ws[256];
    Ws[threadIdx.x] = W[threadIdx.x];
    __syncthreads();
    const size_t S2 = 262144;   // pairs per (b,head); per m: 2048 pairs
    const int b = blockIdx.y;
    const size_t s2 = (size_t)blockIdx.x * 256 + threadIdx.x;
    const int m = (int)(s2 >> 11);
    const int n = (int)(s2 & 2047) * 2;
    const unsigned char mk0 = g_mask[b * 4096 + n];
    const unsigned char mk1 = g_mask[b * 4096 + n + 1];
    float2 v[16];
#pragma unroll
    for (int h = 0; h < 16; h++) {
        float2 raw = bf2f(*(const __nv_bfloat162*)(g_ak + ((size_t)(b * 16 + h) * S2 + s2) * 2));
        float2 st = g_akstat[(b * 16 + h) * 128 + m];
        v[h].x = mk0 ? __expf(raw.x - st.x) * st.y : 0.f;
        v[h].y = mk1 ? __expf(raw.y - st.x) * st.y : 0.f;
    }
#pragma unroll
    for (int g = 0; g < 16; g++) {
        float ox = 0.f, oy = 0.f;
#pragma unroll
        for (int h = 0; h < 16; h++) {
            float w = Ws[g * 16 + h];
            ox += w * v[h].x; oy += w * v[h].y;
        }
        *(__nv_bfloat162*)(g_akm + ((size_t)(b * 16 + g) * S2 + s2) * 2) =
            __floats2bfloat162_rn(ox, oy);
    }
}

// ---------------- agent_out partials: split n into 4 ranges (bf16 akm input) --------
__global__ __launch_bounds__(512) void k_agent_out() {
    __shared__ float akm_s[128 * 64];
    __shared__ float v_s[64 * 64];
    const int g = blockIdx.x, b = blockIdx.y, sp = blockIdx.z;
    const int t = threadIdx.x;
    const int d = t & 63, mg = t >> 6;
    const __nv_bfloat16* akm_b = g_akm + (size_t)(b * 16 + g) * 524288;
    const float* v_b = g_qkv + (size_t)b * 4096 * 3072 + 2048 + g * 64;

    float acc[16];
#pragma unroll
    for (int j = 0; j < 16; j++) acc[j] = 0.f;

    const int nlo = sp * 1024;
    for (int n0 = 0; n0 < 1024; n0 += 64) {
        const int nb = nlo + n0;
#pragma unroll
        for (int i = 0; i < 8; i++) {
            int pidx = t + i * 512;           // pair index: 4096 pairs = 128r x 32cp
            int r = pidx >> 5, cp = pidx & 31;
            float2 vv = bf2f(*(const __nv_bfloat162*)(akm_b + (size_t)r * 4096 + nb + cp * 2));
            *(float2*)&akm_s[r * 64 + cp * 2] = vv;
        }
#pragma unroll
        for (int i = 0; i < 8; i++) {
            int idx = t + i * 512;
            int r = idx >> 6, c = idx & 63;
            v_s[idx] = v_b[(size_t)(nb + r) * 3072 + c];
        }
        __syncthreads();
#pragma unroll 4
        for (int nn = 0; nn < 64; nn++) {
            float vv = v_s[nn * 64 + d];
#pragma unroll
            for (int j = 0; j < 16; j++)
                acc[j] += akm_s[(mg * 16 + j) * 64 + nn] * vv;
        }
        __syncthreads();
    }
    float* out = g_aop + (size_t)sp * 524288 + (size_t)(b * 16 + g) * 8192;
#pragma unroll
    for (int j = 0; j < 16; j++) out[(mg * 16 + j) * 64 + d] = acc[j];
}

__global__ __launch_bounds__(256) void k_ao_reduce() {
    const int i = blockIdx.x * 256 + threadIdx.x;
    g_ao[i] = g_aop[i] + g_aop[524288 + i] + g_aop[1048576 + i] + g_aop[1572864 + i];
}

// ---------------- out_pre FUSED with packed-A epilogue (bf16 qam input) ----------------
__global__ __launch_bounds__(256) void k_out_pre() {
    extern __shared__ float fsm[];
    float* qs = fsm;          // [64m][128n]
    float* aos = fsm + 8192;  // [128m][64d]
    const int n0 = blockIdx.x * 128, g = blockIdx.y, b = blockIdx.z;
    const int t = threadIdx.x;
    const int tx = t & 15, ty = t >> 4;
    const __nv_bfloat16* qam_b = g_qam + (size_t)(b * 16 + g) * 524288;
    const float* ao_b = g_ao + (size_t)(b * 16 + g) * 8192;

#pragma unroll
    for (int i = 0; i < 8; i++) {
        int f = t + i * 256;
        int m = f >> 4, df = (f & 15) * 4;
        *(float4*)&aos[m * 64 + df] = *(const float4*)(ao_b + m * 64 + df);
    }

    float acc[8][4];
#pragma unroll
    for (int i = 0; i < 8; i++)
#pragma unroll
        for (int w = 0; w < 4; w++) acc[i][w] = 0.f;

    for (int mc = 0; mc < 128; mc += 64) {
        __syncthreads();
#pragma unroll
        for (int i = 0; i < 8; i++) {
            int f = t + i * 256;
            int n = f >> 4, mf = (f & 15) * 4;
            const __nv_bfloat16* src = qam_b + (size_t)(n0 + n) * 128 + mc + mf;
            float2 v01 = bf2f(*(const __nv_bfloat162*)(src));
            float2 v23 = bf2f(*(const __nv_bfloat162*)(src + 2));
            qs[(mf + 0) * 128 + n] = v01.x;
            qs[(mf + 1) * 128 + n] = v01.y;
            qs[(mf + 2) * 128 + n] = v23.x;
            qs[(mf + 3) * 128 + n] = v23.y;
        }
        __syncthreads();
#pragma unroll 4
        for (int mm = 0; mm < 64; mm++) {
            float4 r0 = *(const float4*)&qs[mm * 128 + ty * 4];
            float4 r1 = *(const float4*)&qs[mm * 128 + 64 + ty * 4];
            float4 rb = *(const float4*)&aos[(mc + mm) * 64 + tx * 4];
            const float rn[8] = {r0.x, r0.y, r0.z, r0.w, r1.x, r1.y, r1.z, r1.w};
            const float* bw = &rb.x;
#pragma unroll
            for (int i = 0; i < 8; i++)
#pragma unroll
                for (int w = 0; w < 4; w++) acc[i][w] += rn[i] * bw[w];
        }
    }

    // fused packed-A store: k = g*64 + tx*4 + w -> (c, ks, hi) fixed, tig = w
    const int kbase = g * 64 + tx * 4;
    const int kc = kbase >> 5;
    const int ks = (kbase >> 3) & 3;
    const int hi = (kbase >> 2) & 1;
#pragma unroll
    for (int i = 0; i < 8; i++) {
        const int n_i = n0 + ((i < 4) ? (ty * 4 + i) : (64 + ty * 4 + i - 4));
        const float msk = g_mask[b * 4096 + n_i] ? 1.f : 0.f;
        const int r = b * 4096 + n_i;
        const int rowtile = r >> 8, blk = (r >> 4) & 15, gidE = r & 7, hb = (r >> 3) & 1;
        const int j = hi * 2 + hb;
        float* base = g_pA + ((size_t)rowtile * 32 + kc) * 8192;
#pragma unroll
        for (int w = 0; w < 4; w++) {
            const int lane = (gidE * 4 + w) ^ ks;
            base[((blk * 4 + ks) * 32 + lane) * 4 + j] =
                __uint_as_float(f2tf32(acc[i][w] * msk));
        }
    }
}

// ---------------- launch ----------------
extern "C" void kernel_launch(void* const* d_in, const int* in_sizes, int n_in,
                              void* d_out, int out_size) {
    const float* x = (const float*)d_in[0];
    const void* mask_raw = d_in[1];
    const float* W_qkv = (const float*)d_in[2];
    const float* agent = (const float*)d_in[3];
    const float* W_qa = (const float*)d_in[4];
    const float* W_ak = (const float*)d_in[5];
    const float* W_out = (const float*)d_in[6];
    float* out = (float*)d_out;

    cudaFuncSetAttribute(k_gemm_qkv, cudaFuncAttributeMaxDynamicSharedMemorySize, G3_SMEM_BYTES);
    cudaFuncSetAttribute(k_gemm_out, cudaFuncAttributeMaxDynamicSharedMemorySize, G3_SMEM_BYTES);
    cudaFuncSetAttribute(k_sims, cudaFuncAttributeMaxDynamicSharedMemorySize, 65536);
    cudaFuncSetAttribute(k_out_pre, cudaFuncAttributeMaxDynamicSharedMemorySize, 65536);

    // launch order chosen so k_gemm_qkv is the 4th launch (profiled slot)
    k_mask_canon<<<1, 256>>>(mask_raw);
    k_packB_qkv<<<3072, 256>>>(W_qkv);
    k_packA_x<<<16384, 256>>>(x);
    // 4th launch: profiled
    k_gemm_qkv<<<dim3(3072 / 128, 16384 / 128), 128, G3_SMEM_BYTES>>>();
    k_packB_out<<<1024, 256>>>(W_out);
    // merged qa (+softmax) and ak sims
    k_sims<<<dim3(32, 16, 4), 256, 65536>>>(agent);
    k_ak_stats<<<8192, 256>>>();
    k_mix_qa<<<dim3(1024, 4), 256>>>(W_qa);
    k_mix_ak<<<dim3(1024, 4), 256>>>(W_ak);
    k_agent_out<<<dim3(16, 4, 4), 512>>>();
    k_ao_reduce<<<2048, 256>>>();
    k_out_pre<<<dim3(32, 16, 4), 256, 65536>>>();
    k_gemm_out<<<dim3(1024 / 128, 16384 / 128), 128, G3_SMEM_BYTES>>>(out);
}